// round 14
// baseline (speedup 1.0000x reference)
#include <cuda_runtime.h>
#include <cuda_bf16.h>
#include <math.h>
#include <stdint.h>

#define Bn 16384
#define Dn 512
#define Kn 16384
#define Hn 256
#define Zn 128
#define LDK2 136                     // padded row stride in bf16 (272B); bytes 256..259 carry -0.5||c||^2

// ---------------- scratch ----------------
__device__ __align__(16) float g_enc[(size_t)Bn * Zn];
__device__ __align__(16) __nv_bfloat16 g_e0p[(size_t)Bn * LDK2];
__device__ __align__(16) __nv_bfloat16 g_c0p[(size_t)Kn * LDK2];
__device__ float g_negc2[Kn];
__device__ float g_en2[Bn];
__device__ float g_dn2[Bn];
__device__ float g_Rmax2;
__device__ float g_Nmax2;
__device__ float g_smax[Bn];
__device__ float g_cand_val[(size_t)Bn * 48];
__device__ int   g_cand_idx[(size_t)Bn * 48];
__device__ float g_fourth[(size_t)Bn * 16];
__device__ int   g_idx[Bn];
__device__ float g_err[Bn];
__device__ float g_sum;
// W4 pre-packed B-fragments: [s(16)][j(64)][p(2)][lane(32)] of uint2
__device__ __align__(16) uint2 g_W4f[16 * 64 * 2 * 32];
// k-pair packed weights: pair p holds (W[2p][c], W[2p+1][c]) as f32x2
__device__ __align__(16) uint64_t g_W1k[256 * 256];   // W1 [512,256]
__device__ __align__(16) uint64_t g_W2k[128 * 128];   // W2 [256,128]
__device__ __align__(16) uint64_t g_W3k[64 * 256];    // W3 [128,256]

// ---------------- helpers ----------------
__device__ __forceinline__ uint32_t smem_u32(const void* p) {
    uint32_t a;
    asm("{ .reg .u64 t; cvta.to.shared.u64 t, %1; cvt.u32.u64 %0, t; }" : "=r"(a) : "l"(p));
    return a;
}
__device__ __forceinline__ void ldsm_x4(uint32_t r[4], uint32_t addr) {
    asm volatile("ldmatrix.sync.aligned.m8n8.x4.shared.b16 {%0,%1,%2,%3}, [%4];"
        : "=r"(r[0]), "=r"(r[1]), "=r"(r[2]), "=r"(r[3]) : "r"(addr));
}
__device__ __forceinline__ void mma_bf16(float d[4], const uint32_t a[4], const uint32_t b[2]) {
    asm volatile("mma.sync.aligned.m16n8k16.row.col.f32.bf16.bf16.f32 "
        "{%0,%1,%2,%3}, {%4,%5,%6,%7}, {%8,%9}, {%0,%1,%2,%3};"
        : "+f"(d[0]), "+f"(d[1]), "+f"(d[2]), "+f"(d[3])
        : "r"(a[0]), "r"(a[1]), "r"(a[2]), "r"(a[3]), "r"(b[0]), "r"(b[1]));
}
__device__ __forceinline__ uint32_t pack_bf16(float a, float b) {
    __nv_bfloat162 t = __floats2bfloat162_rn(a, b);
    return *(uint32_t*)&t;
}
__device__ __forceinline__ void fma_f32x2(uint64_t& d, uint64_t a, uint64_t b) {
    asm("fma.rn.f32x2 %0, %1, %2, %0;" : "+l"(d) : "l"(a), "l"(b));
}
__device__ __forceinline__ void unpackf2(float& lo, float& hi, uint64_t v) {
    asm("mov.b64 {%0, %1}, %2;" : "=f"(lo), "=f"(hi) : "l"(v));
}
__device__ __forceinline__ uint64_t packu64(float a, float b) {
    return ((uint64_t)__float_as_uint(b) << 32) | (uint64_t)__float_as_uint(a);
}
__device__ __forceinline__ void bulk_g2s(uint32_t dst, const void* src, uint32_t bytes, uint32_t mbar) {
    asm volatile("cp.async.bulk.shared::cluster.global.mbarrier::complete_tx::bytes [%0], [%1], %2, [%3];"
        :: "r"(dst), "l"(src), "r"(bytes), "r"(mbar) : "memory");
}
#define MBAR_INIT(mb, c) \
    asm volatile("mbarrier.init.shared.b64 [%0], %1;" :: "r"((uint32_t)(mb)), "r"((uint32_t)(c)) : "memory")
#define MBAR_EXPECT_TX(mb, n) \
    asm volatile("mbarrier.arrive.expect_tx.shared.b64 _, [%0], %1;" :: "r"((uint32_t)(mb)), "r"((uint32_t)(n)) : "memory")
#define MBAR_ARRIVE(mb) \
    asm volatile("mbarrier.arrive.shared.b64 _, [%0];" :: "r"((uint32_t)(mb)) : "memory")
#define MBAR_WAIT(mb, par) do { \
    uint32_t _m = (uint32_t)(mb); uint32_t _p = (uint32_t)(par); uint32_t _d; \
    asm volatile("{\n\t.reg .pred p;\n\t" \
        "mbarrier.try_wait.parity.acquire.cta.shared::cta.b64 p, [%1], %2;\n\t" \
        "selp.b32 %0, 1, 0, p;\n\t}" : "=r"(_d) : "r"(_m), "r"(_p) : "memory"); \
    if (!_d) { \
        asm volatile("{\n\t.reg .pred P1;\n\t" \
            "WL_%=:\n\t" \
            "mbarrier.try_wait.parity.acquire.cta.shared::cta.b64 P1, [%0], %1, 0x989680;\n\t" \
            "@P1 bra.uni WD_%=;\n\tbra.uni WL_%=;\n\tWD_%=:\n\t}" \
            :: "r"(_m), "r"(_p) : "memory"); \
    } } while (0)

// ---------------- weight k-pair prep (W1, W2, W3) ----------------
__global__ void wprep_kernel(const float* __restrict__ W1,
                             const float* __restrict__ W2,
                             const float* __restrict__ W3)
{
    int i = blockIdx.x * 256 + threadIdx.x;   // 98304 total
    if (i < 65536) {
        int p = i >> 8, c = i & 255;
        g_W1k[i] = packu64(W1[(2 * p) * Hn + c], W1[(2 * p + 1) * Hn + c]);
    } else if (i < 81920) {
        int j = i - 65536;
        int p = j >> 7, c = j & 127;
        g_W2k[j] = packu64(W2[(2 * p) * Zn + c], W2[(2 * p + 1) * Zn + c]);
    } else {
        int j = i - 81920;
        int p = j >> 8, c = j & 255;
        g_W3k[j] = packu64(W3[(2 * p) * Hn + c], W3[(2 * p + 1) * Hn + c]);
    }
}

// ---------------- encoder (k-packed f32x2 GEMMs) ----------------
__global__ __launch_bounds__(256, 2) void encoder_kernel(
                               const float* __restrict__ X,
                               const float* __restrict__ b1,
                               const float* __restrict__ g1, const float* __restrict__ be1,
                               const float* __restrict__ b2)
{
    extern __shared__ float sm[];
    float* Xs = sm;
    float* Hs = sm + 32 * Dn;
    const int tid = threadIdx.x;
    const int row0 = blockIdx.x * 32;

    {
        const float4* Xg = (const float4*)(X + (size_t)row0 * Dn);
        float4* Xs4 = (float4*)Xs;
        for (int i = tid; i < 32 * Dn / 4; i += 256) Xs4[i] = Xg[i];
    }
    __syncthreads();

    // GEMM1: thread -> col tid, 32 rows; k-pair packed accumulators
    {
        const ulonglong2* Xs2 = (const ulonglong2*)Xs;
        const int c = tid;
        uint64_t acc2[32];
#pragma unroll
        for (int r = 0; r < 32; ++r) acc2[r] = 0ull;
#pragma unroll 2
        for (int d4 = 0; d4 < Dn / 4; ++d4) {
            uint64_t wp0 = g_W1k[(2 * d4) * Hn + c];
            uint64_t wp1 = g_W1k[(2 * d4 + 1) * Hn + c];
#pragma unroll
            for (int r = 0; r < 32; ++r) {
                ulonglong2 xp = Xs2[(r * Dn) / 4 + d4];
                fma_f32x2(acc2[r], xp.x, wp0);
                fma_f32x2(acc2[r], xp.y, wp1);
            }
        }
        float bb = b1[c];
#pragma unroll
        for (int r = 0; r < 32; ++r) {
            float lo, hi;
            unpackf2(lo, hi, acc2[r]);
            Hs[r * Hn + c] = lo + hi + bb;
        }
    }
    __syncthreads();

    // LN + GELU
    {
        const int warp = tid >> 5, lane = tid & 31;
        for (int rr = 0; rr < 4; ++rr) {
            int r = warp + rr * 8;
            float s = 0.f, s2 = 0.f;
#pragma unroll
            for (int j = 0; j < 8; ++j) {
                float v = Hs[r * Hn + lane + j * 32];
                s += v; s2 += v * v;
            }
#pragma unroll
            for (int o = 16; o > 0; o >>= 1) {
                s  += __shfl_xor_sync(0xffffffff, s,  o);
                s2 += __shfl_xor_sync(0xffffffff, s2, o);
            }
            float mu  = s * (1.f / Hn);
            float var = s2 * (1.f / Hn) - mu * mu;
            float inv = rsqrtf(var + 1e-5f);
#pragma unroll
            for (int j = 0; j < 8; ++j) {
                int c = lane + j * 32;
                float v = (Hs[r * Hn + c] - mu) * inv * g1[c] + be1[c];
                Hs[r * Hn + c] = 0.5f * v * (1.f + erff(v * 0.70710678118654752f));
            }
        }
    }
    __syncthreads();

    // GEMM2: thread -> col (tid&127), rows rbase..rbase+15; k-pair packed
    {
        const ulonglong2* Hs2 = (const ulonglong2*)Hs;
        const int c2 = tid & 127;
        const int rbase = (tid >> 7) * 16;
        uint64_t acc2[16];
#pragma unroll
        for (int r = 0; r < 16; ++r) acc2[r] = 0ull;
#pragma unroll 2
        for (int d4 = 0; d4 < Hn / 4; ++d4) {
            uint64_t wp0 = g_W2k[(2 * d4) * Zn + c2];
            uint64_t wp1 = g_W2k[(2 * d4 + 1) * Zn + c2];
#pragma unroll
            for (int r = 0; r < 16; ++r) {
                ulonglong2 hp = Hs2[((rbase + r) * Hn) / 4 + d4];
                fma_f32x2(acc2[r], hp.x, wp0);
                fma_f32x2(acc2[r], hp.y, wp1);
            }
        }
        float bb = b2[c2];
#pragma unroll
        for (int r = 0; r < 16; ++r) {
            float lo, hi;
            unpackf2(lo, hi, acc2[r]);
            g_enc[(size_t)(row0 + rbase + r) * Zn + c2] = lo + hi + bb;
        }
    }
}

// ---------------- per-row e0 (padded) + norms ----------------
__global__ void enorm_kernel()
{
    int gw = (blockIdx.x * 256 + threadIdx.x) >> 5;
    int lane = threadIdx.x & 31;
    const float4 e4 = ((const float4*)(g_enc + (size_t)gw * 128))[lane];
    float e0x = __bfloat162float(__float2bfloat16(e4.x));
    float e0y = __bfloat162float(__float2bfloat16(e4.y));
    float e0z = __bfloat162float(__float2bfloat16(e4.z));
    float e0w = __bfloat162float(__float2bfloat16(e4.w));
    *(uint2*)(g_e0p + (size_t)gw * LDK2 + lane * 4) =
        make_uint2(pack_bf16(e4.x, e4.y), pack_bf16(e4.z, e4.w));
    float en2 = e4.x*e4.x + e4.y*e4.y + e4.z*e4.z + e4.w*e4.w;
    float dx = e4.x - e0x, dy = e4.y - e0y, dz = e4.z - e0z, dw = e4.w - e0w;
    float dn2 = dx*dx + dy*dy + dz*dz + dw*dw;
#pragma unroll
    for (int o = 16; o > 0; o >>= 1) {
        en2 += __shfl_xor_sync(0xffffffff, en2, o);
        dn2 += __shfl_xor_sync(0xffffffff, dn2, o);
    }
    if (lane == 0) { g_en2[gw] = en2; g_dn2[gw] = dn2; }
}

// ---------------- codebook prep (padded; nc stashed in row padding) ----------------
__global__ void c0split_kernel(const float* __restrict__ C)
{
    int code = (blockIdx.x * 256 + threadIdx.x) >> 5;
    int lane = threadIdx.x & 31;
    const float4 c4 = ((const float4*)(C + (size_t)code * 128))[lane];
    float c0x = __bfloat162float(__float2bfloat16(c4.x));
    float c0y = __bfloat162float(__float2bfloat16(c4.y));
    float c0z = __bfloat162float(__float2bfloat16(c4.z));
    float c0w = __bfloat162float(__float2bfloat16(c4.w));
    *(uint2*)(g_c0p + (size_t)code * LDK2 + lane * 4) =
        make_uint2(pack_bf16(c4.x, c4.y), pack_bf16(c4.z, c4.w));
    float c2 = c4.x*c4.x + c4.y*c4.y + c4.z*c4.z + c4.w*c4.w;
    float n2 = c0x*c0x + c0y*c0y + c0z*c0z + c0w*c0w;
    float dx = c4.x - c0x, dy = c4.y - c0y, dz = c4.z - c0z, dw = c4.w - c0w;
    float r2 = dx*dx + dy*dy + dz*dz + dw*dw;
#pragma unroll
    for (int o = 16; o > 0; o >>= 1) {
        c2 += __shfl_xor_sync(0xffffffff, c2, o);
        n2 += __shfl_xor_sync(0xffffffff, n2, o);
        r2 += __shfl_xor_sync(0xffffffff, r2, o);
    }
    if (lane == 0) {
        float nc = -0.5f * c2;
        g_negc2[code] = nc;
        *(float*)((char*)g_c0p + (size_t)code * (LDK2 * 2) + 256) = nc;
        atomicMax((int*)&g_Rmax2, __float_as_int(r2));
        atomicMax((int*)&g_Nmax2, __float_as_int(n2));
    }
}

// ---------------- W4 fragment pre-pack (2-way bf16 split, B-frag order) ----------------
__global__ void w4split_kernel(const float* __restrict__ W4)
{
    int i = blockIdx.x * 256 + threadIdx.x;
    int lane = i & 31;
    int p = (i >> 5) & 1;
    int j = (i >> 6) & 63;
    int s = i >> 12;
    int n = j * 8 + (lane >> 2);
    uint32_t regs[2];
#pragma unroll
    for (int r = 0; r < 2; ++r) {
        int k = s * 16 + (lane & 3) * 2 + r * 8;
        float wa = W4[(size_t)k * Dn + n];
        float wb = W4[(size_t)(k + 1) * Dn + n];
        float va, vb;
        if (p == 0) {
            va = __bfloat162float(__float2bfloat16(wa));
            vb = __bfloat162float(__float2bfloat16(wb));
        } else {
            va = wa - __bfloat162float(__float2bfloat16(wa));
            vb = wb - __bfloat162float(__float2bfloat16(wb));
        }
        regs[r] = pack_bf16(va, vb);
    }
    g_W4f[i] = make_uint2(regs[0], regs[1]);
}

// ---------------- coarse distance: mbarrier ring; nc folded into acc init ----------------
#define A_BYTES (64 * LDK2 * 2)
#define TILE_BYTES (128 * LDK2 * 2)
#define SB_A 0
#define SB_B0 A_BYTES
#define SB_MBAR (A_BYTES + 2 * TILE_BYTES)
#define SB_RED (SB_MBAR + 64)
#define DSM2_TOT (SB_RED + 64 * 16 * 4)

__global__ __launch_bounds__(256, 2) void dist_coarse_kernel()
{
    extern __shared__ char smem[];
    float* redsm = (float*)(smem + SB_RED);

    const int tid  = threadIdx.x;
    const int lane = tid & 31;
    const int wid  = tid >> 5;
    const int warp_m = wid >> 2;
    const int warp_n = wid & 3;
    const int row0 = blockIdx.x * 64;

    const uint32_t sbA    = smem_u32(smem) + SB_A;
    const uint32_t sbB0   = smem_u32(smem) + SB_B0;
    const uint32_t mbA    = smem_u32(smem) + SB_MBAR;
    const uint32_t mbF0   = mbA + 8;
    const uint32_t mbF1   = mbA + 16;
    const uint32_t mbE0   = mbA + 24;
    const uint32_t mbE1   = mbA + 32;

    if (tid == 0) {
        MBAR_INIT(mbA, 1);
        MBAR_INIT(mbF0, 1);
        MBAR_INIT(mbF1, 1);
        MBAR_INIT(mbE0, 8);
        MBAR_INIT(mbE1, 8);
    }
    __syncthreads();

    if (tid == 0) {
        MBAR_EXPECT_TX(mbA, A_BYTES);
        bulk_g2s(sbA, g_e0p + (size_t)row0 * LDK2, A_BYTES, mbA);
        MBAR_EXPECT_TX(mbF0, TILE_BYTES);
        bulk_g2s(sbB0, g_c0p, TILE_BYTES, mbF0);
    }

    uint32_t a_addr[2];
#pragma unroll
    for (int mi = 0; mi < 2; ++mi)
        a_addr[mi] = sbA + ((warp_m * 32 + mi * 16 + (lane & 15)) * LDK2 + (lane >> 4) * 8) * 2;
    uint32_t b_addr[2];
#pragma unroll
    for (int njp = 0; njp < 2; ++njp)
        b_addr[njp] = sbB0 + ((warp_n * 32 + njp * 16 + (lane & 7) + ((lane >> 4) << 3)) * LDK2
                              + ((lane >> 3) & 1) * 8) * 2;

    float v1[4], v2[4], v3[4], v4[4];
    int   i1[4], i2[4], i3[4];
#pragma unroll
    for (int r = 0; r < 4; ++r) {
        v1[r] = v2[r] = v3[r] = v4[r] = -INFINITY;
        i1[r] = i2[r] = i3[r] = 0;
    }

    const int cq = (lane & 3) * 2;

    MBAR_WAIT(mbA, 0);

    for (int t = 0, kt = 0; t < 128; ++t, kt += 128) {
        const uint32_t bufo = (uint32_t)(t & 1) * TILE_BYTES;

        if (tid == 0 && t < 127) {
            const int tn = t + 1;
            const int bn = tn & 1;
            const int f  = tn >> 1;
            uint32_t mbE = bn ? mbE1 : mbE0;
            uint32_t mbF = bn ? mbF1 : mbF0;
            if (f > 0) MBAR_WAIT(mbE, (f & 1) ^ 1);
            MBAR_EXPECT_TX(mbF, TILE_BYTES);
            bulk_g2s(sbB0 + (uint32_t)bn * TILE_BYTES,
                     g_c0p + (size_t)(kt + 128) * LDK2, TILE_BYTES, mbF);
        }

        MBAR_WAIT((t & 1) ? mbF1 : mbF0, (t >> 1) & 1);

        float nc[8];
#pragma unroll
        for (int nj = 0; nj < 4; ++nj) {
#pragma unroll
            for (int q = 0; q < 2; ++q) {
                asm volatile("ld.shared.f32 %0, [%1];"
                    : "=f"(nc[nj * 2 + q])
                    : "r"(sbB0 + bufo + (uint32_t)(warp_n * 32 + nj * 8 + cq + q) * (LDK2 * 2) + 256));
            }
        }

        float acc[2][4][4];
#pragma unroll
        for (int mi = 0; mi < 2; ++mi)
#pragma unroll
            for (int nj = 0; nj < 4; ++nj)
#pragma unroll
                for (int k = 0; k < 4; ++k) acc[mi][nj][k] = nc[nj * 2 + (k & 1)];

#pragma unroll
        for (int s = 0; s < 8; ++s) {
            uint32_t af[2][4], bf[2][4];
#pragma unroll
            for (int mi = 0; mi < 2; ++mi) ldsm_x4(af[mi], a_addr[mi] + s * 32);
#pragma unroll
            for (int njp = 0; njp < 2; ++njp) ldsm_x4(bf[njp], b_addr[njp] + bufo + s * 32);
#pragma unroll
            for (int mi = 0; mi < 2; ++mi)
#pragma unroll
                for (int nj = 0; nj < 4; ++nj)
                    mma_bf16(acc[mi][nj], af[mi], bf[nj >> 1] + (nj & 1) * 2);
        }

        if (lane == 0) MBAR_ARRIVE((t & 1) ? mbE1 : mbE0);

#pragma unroll
        for (int mi = 0; mi < 2; ++mi) {
#pragma unroll
            for (int h = 0; h < 2; ++h) {
                const int ri = mi * 2 + h;
                float s0 = acc[mi][0][h * 2];
                float s1 = acc[mi][0][h * 2 + 1];
                float s2 = acc[mi][1][h * 2];
                float s3 = acc[mi][1][h * 2 + 1];
                float s4 = acc[mi][2][h * 2];
                float s5 = acc[mi][2][h * 2 + 1];
                float s6 = acc[mi][3][h * 2];
                float s7 = acc[mi][3][h * 2 + 1];
                float m8 = fmaxf(fmaxf(fmaxf(s0, s1), fmaxf(s2, s3)),
                                 fmaxf(fmaxf(s4, s5), fmaxf(s6, s7)));
                if (m8 > v4[ri]) {
                    float sv[8] = {s0, s1, s2, s3, s4, s5, s6, s7};
#pragma unroll
                    for (int j = 0; j < 8; ++j) {
                        float v = sv[j];
                        if (v > v4[ri]) {
                            int idx = kt + warp_n * 32 + (j >> 1) * 8 + cq + (j & 1);
                            if (v > v1[ri]) {
                                v4[ri] = v3[ri]; v3[ri] = v2[ri]; i3[ri] = i2[ri];
                                v2[ri] = v1[ri]; i2[ri] = i1[ri];
                                v1[ri] = v; i1[ri] = idx;
                            } else if (v > v2[ri]) {
                                v4[ri] = v3[ri]; v3[ri] = v2[ri]; i3[ri] = i2[ri];
                                v2[ri] = v; i2[ri] = idx;
                            } else if (v > v3[ri]) {
                                v4[ri] = v3[ri]; v3[ri] = v; i3[ri] = idx;
                            } else {
                                v4[ri] = v;
                            }
                        }
                    }
                }
            }
        }
    }

    const int slot = warp_n * 4 + (lane & 3);
#pragma unroll
    for (int ri = 0; ri < 4; ++ri) {
        int mi = ri >> 1, h = ri & 1;
        int lrow = warp_m * 32 + mi * 16 + (lane >> 2) + h * 8;
        size_t row = (size_t)(row0 + lrow);
        g_cand_val[row * 48 + slot * 3]     = v1[ri];
        g_cand_idx[row * 48 + slot * 3]     = i1[ri];
        g_cand_val[row * 48 + slot * 3 + 1] = v2[ri];
        g_cand_idx[row * 48 + slot * 3 + 1] = i2[ri];
        g_cand_val[row * 48 + slot * 3 + 2] = v3[ri];
        g_cand_idx[row * 48 + slot * 3 + 2] = i3[ri];
        g_fourth[row * 16 + slot] = v4[ri];
        redsm[lrow * 16 + slot] = v1[ri];
    }
    __syncthreads();
    if (tid < 64) {
        float m = redsm[tid * 16];
#pragma unroll
        for (int w = 1; w < 16; ++w) m = fmaxf(m, redsm[tid * 16 + w]);
        g_smax[row0 + tid] = m;
    }
}

// ---------------- exact rescore (warp per row) ----------------
__global__ void rescore_kernel(const float* __restrict__ CB)
{
    const int r = blockIdx.x * 4 + (threadIdx.x >> 5);
    const int lane = threadIdx.x & 31;

    float delta = sqrtf(g_en2[r]) * sqrtf(g_Rmax2) + sqrtf(g_dn2[r]) * sqrtf(g_Nmax2);
    float thresh = g_smax[r] - 1.05f * delta - 1e-4f;

    float th = (lane < 16) ? g_fourth[(size_t)r * 16 + lane] : -INFINITY;
    bool flag = __ballot_sync(0xffffffff, th >= thresh) != 0;

    const float4 e4 = ((const float4*)(g_enc + (size_t)r * 128))[lane];

    float bs = -INFINITY;
    int bi = 0x7fffffff;

    if (!flag) {
        for (int s = 0; s < 48; ++s) {
            float v = g_cand_val[(size_t)r * 48 + s];
            if (v >= thresh) {
                int idx = g_cand_idx[(size_t)r * 48 + s];
                float4 c4 = ((const float4*)(CB + (size_t)idx * 128))[lane];
                float d = e4.x*c4.x + e4.y*c4.y + e4.z*c4.z + e4.w*c4.w;
#pragma unroll
                for (int o = 16; o > 0; o >>= 1) d += __shfl_xor_sync(0xffffffff, d, o);
                float sx = d + g_negc2[idx];
                if (sx > bs || (sx == bs && idx < bi)) { bs = sx; bi = idx; }
            }
        }
    } else {
        for (int k = 0; k < Kn; ++k) {
            float4 c4 = ((const float4*)(CB + (size_t)k * 128))[lane];
            float d = e4.x*c4.x + e4.y*c4.y + e4.z*c4.z + e4.w*c4.w;
#pragma unroll
            for (int o = 16; o > 0; o >>= 1) d += __shfl_xor_sync(0xffffffff, d, o);
            float sx = d + g_negc2[k];
            if (sx > bs) { bs = sx; bi = k; }
        }
    }
    if (lane == 0) g_idx[r] = bi;
}

// ---------------- decoder: k-packed f32x2 GEMM1, mma GEMM2 ----------------
#define DEC_HS0_OFF (32 * Zn + 32 * Hn)
#define DEC_LDH 264
#define DEC_SMEM (12288 * 4 + 2 * 32 * DEC_LDH * 2 + 32 * 8 * 4)

__global__ void decoder_kernel(const float* __restrict__ C,
                               const float* __restrict__ b3,
                               const float* __restrict__ g2, const float* __restrict__ be2,
                               const float* __restrict__ b4,
                               const float* __restrict__ X)
{
    extern __shared__ float sm[];
    float* Qs = sm;
    float* Hs = sm + 32 * Zn;
    __nv_bfloat16* Hs0 = (__nv_bfloat16*)(sm + DEC_HS0_OFF);
    __nv_bfloat16* Hs1 = Hs0 + 32 * DEC_LDH;
    float* ep = (float*)(Hs1 + 32 * DEC_LDH);
    const int tid = threadIdx.x;
    const int lane = tid & 31;
    const int wid = tid >> 5;
    const int row0 = blockIdx.x * 32;

    for (int i = tid; i < 32 * 32; i += 256) {
        int r = i >> 5, d4 = i & 31;
        int code = g_idx[row0 + r];
        ((float4*)Qs)[r * 32 + d4] = ((const float4*)C)[(size_t)code * 32 + d4];
    }
    __syncthreads();

    // k-packed f32x2 GEMM1: thread -> col tid, 32 rows
    {
        const ulonglong2* Qs2 = (const ulonglong2*)Qs;
        const int c = tid;
        uint64_t acc2[32];
#pragma unroll
        for (int r = 0; r < 32; ++r) acc2[r] = 0ull;
#pragma unroll 2
        for (int d4 = 0; d4 < Zn / 4; ++d4) {
            uint64_t wp0 = g_W3k[(2 * d4) * Hn + c];
            uint64_t wp1 = g_W3k[(2 * d4 + 1) * Hn + c];
#pragma unroll
            for (int r = 0; r < 32; ++r) {
                ulonglong2 qp = Qs2[(r * Zn) / 4 + d4];
                fma_f32x2(acc2[r], qp.x, wp0);
                fma_f32x2(acc2[r], qp.y, wp1);
            }
        }
        float bb = b3[c];
#pragma unroll
        for (int r = 0; r < 32; ++r) {
            float lo, hi;
            unpackf2(lo, hi, acc2[r]);
            Hs[r * Hn + c] = lo + hi + bb;
        }
    }
    __syncthreads();

    {
        for (int rr = 0; rr < 4; ++rr) {
            int r = wid + rr * 8;
            float s = 0.f, s2 = 0.f;
#pragma unroll
            for (int j = 0; j < 8; ++j) {
                float v = Hs[r * Hn + lane + j * 32];
                s += v; s2 += v * v;
            }
#pragma unroll
            for (int o = 16; o > 0; o >>= 1) {
                s  += __shfl_xor_sync(0xffffffff, s,  o);
                s2 += __shfl_xor_sync(0xffffffff, s2, o);
            }
            float mu  = s * (1.f / Hn);
            float var = s2 * (1.f / Hn) - mu * mu;
            float inv = rsqrtf(var + 1e-5f);
#pragma unroll
            for (int j = 0; j < 8; ++j) {
                int c = lane + j * 32;
                float v = (Hs[r * Hn + c] - mu) * inv * g2[c] + be2[c];
                Hs[r * Hn + c] = 0.5f * v * (1.f + erff(v * 0.70710678118654752f));
            }
        }
    }
    __syncthreads();

    for (int i = tid; i < 32 * 256; i += 256) {
        int r = i >> 8, c = i & 255;
        float f = Hs[r * Hn + c];
        __nv_bfloat16 h0 = __float2bfloat16(f);
        Hs0[r * DEC_LDH + c] = h0;
        Hs1[r * DEC_LDH + c] = __float2bfloat16(f - __bfloat162float(h0));
    }
    __syncthreads();

    {
        const uint32_t h0b = smem_u32(Hs0);
        const uint32_t h1b = smem_u32(Hs1);
        uint32_t a0_addr[2], a1_addr[2];
#pragma unroll
        for (int mi = 0; mi < 2; ++mi) {
            uint32_t off = (uint32_t)((mi * 16 + (lane & 15)) * DEC_LDH * 2 + (lane >> 4) * 16);
            a0_addr[mi] = h0b + off;
            a1_addr[mi] = h1b + off;
        }

        float e_part[2][2] = {{0.f, 0.f}, {0.f, 0.f}};

#pragma unroll
        for (int h2 = 0; h2 < 2; ++h2) {
            float acc[2][4][4];
#pragma unroll
            for (int mi = 0; mi < 2; ++mi)
#pragma unroll
                for (int nj = 0; nj < 4; ++nj)
#pragma unroll
                    for (int k = 0; k < 4; ++k) acc[mi][nj][k] = 0.f;

            const int j0 = wid * 8 + h2 * 4;
            for (int s = 0; s < 16; ++s) {
                uint32_t a0[2][4], a1[2][4];
#pragma unroll
                for (int mi = 0; mi < 2; ++mi) {
                    ldsm_x4(a0[mi], a0_addr[mi] + s * 32);
                    ldsm_x4(a1[mi], a1_addr[mi] + s * 32);
                }
                uint32_t b0[4][2], b1[4][2];
#pragma unroll
                for (int nj = 0; nj < 4; ++nj) {
                    uint2 v = g_W4f[(size_t)(((s * 64 + j0 + nj) * 2 + 0) * 32 + lane)];
                    b0[nj][0] = v.x; b0[nj][1] = v.y;
                    uint2 w = g_W4f[(size_t)(((s * 64 + j0 + nj) * 2 + 1) * 32 + lane)];
                    b1[nj][0] = w.x; b1[nj][1] = w.y;
                }
#pragma unroll
                for (int mi = 0; mi < 2; ++mi)
#pragma unroll
                    for (int nj = 0; nj < 4; ++nj) {
                        mma_bf16(acc[mi][nj], a0[mi], b0[nj]);
                        mma_bf16(acc[mi][nj], a1[mi], b0[nj]);
                        mma_bf16(acc[mi][nj], a0[mi], b1[nj]);
                    }
            }

#pragma unroll
            for (int nj = 0; nj < 4; ++nj) {
                int col = wid * 64 + h2 * 32 + nj * 8 + (lane & 3) * 2;
                float2 bb = *(const float2*)(b4 + col);
#pragma unroll
                for (int mi = 0; mi < 2; ++mi) {
#pragma unroll
                    for (int hr = 0; hr < 2; ++hr) {
                        int rowg = row0 + mi * 16 + (lane >> 2) + hr * 8;
                        float2 xx = *(const float2*)(X + (size_t)rowg * Dn + col);
                        float d0 = acc[mi][nj][hr * 2]     + bb.x - xx.x;
                        float d1 = acc[mi][nj][hr * 2 + 1] + bb.y - xx.y;
                        e_part[mi][hr] += d0 * d0 + d1 * d1;
                    }
                }
            }
        }

#pragma unroll
        for (int mi = 0; mi < 2; ++mi)
#pragma unroll
            for (int hr = 0; hr < 2; ++hr) {
                float v = e_part[mi][hr];
                v += __shfl_xor_sync(0xffffffff, v, 1);
                v += __shfl_xor_sync(0xffffffff, v, 2);
                if ((lane & 3) == 0)
                    ep[(mi * 16 + (lane >> 2) + hr * 8) * 8 + wid] = v;
            }
    }
    __syncthreads();
    if (tid < 32) {
        float s = 0.f;
#pragma unroll
        for (int w = 0; w < 8; ++w) s += ep[tid * 8 + w];
        g_err[row0 + tid] = s * (1.f / Dn);
    }
}

// ---------------- global mean ----------------
__global__ void reduce_kernel()
{
    __shared__ float s[256];
    int tid = threadIdx.x;
    float a = 0.f;
    for (int i = tid; i < Bn; i += 256) a += g_err[i];
    s[tid] = a;
    __syncthreads();
    for (int o = 128; o > 0; o >>= 1) {
        if (tid < o) s[tid] += s[tid + o];
        __syncthreads();
    }
    if (tid == 0) g_sum = s[0];
}

// ---------------- MDL + output ----------------
__global__ void final_kernel(float* __restrict__ out)
{
    int i = blockIdx.x * 256 + threadIdx.x;
    float scale = g_sum * (1.f / Bn) + 1e-8f;
    float err = g_err[i];
    float eb = (fabsf(err) / scale + logf(2.f * scale)) * 1.4426950408889634f;
    float tb = 14.f + eb;
    out[i]          = err;
    out[Bn + i]     = (Dn * 32.f) / tb;
    out[2 * Bn + i] = tb;
    out[3 * Bn + i] = (float)g_idx[i];
}

// ---------------- launch ----------------
extern "C" void kernel_launch(void* const* d_in, const int* in_sizes, int n_in,
                              void* d_out, int out_size)
{
    const float* X   = (const float*)d_in[0];
    const float* W1  = (const float*)d_in[1];
    const float* b1  = (const float*)d_in[2];
    const float* g1  = (const float*)d_in[3];
    const float* be1 = (const float*)d_in[4];
    const float* W2  = (const float*)d_in[5];
    const float* b2  = (const float*)d_in[6];
    const float* CB  = (const float*)d_in[7];
    const float* W3  = (const float*)d_in[8];
    const float* b3  = (const float*)d_in[9];
    const float* g2  = (const float*)d_in[10];
    const float* be2 = (const float*)d_in[11];
    const float* W4  = (const float*)d_in[12];
    const float* b4  = (const float*)d_in[13];
    float* out = (float*)d_out;

    cudaFuncSetAttribute(encoder_kernel,     cudaFuncAttributeMaxDynamicSharedMemorySize, 98304);
    cudaFuncSetAttribute(dist_coarse_kernel, cudaFuncAttributeMaxDynamicSharedMemorySize, DSM2_TOT);
    cudaFuncSetAttribute(decoder_kernel,     cudaFuncAttributeMaxDynamicSharedMemorySize, DEC_SMEM);

    wprep_kernel<<<384, 256>>>(W1, W2, W3);
    c0split_kernel<<<Kn / 8, 256>>>(CB);
    w4split_kernel<<<256, 256>>>(W4);
    encoder_kernel<<<Bn / 32, 256, 98304>>>(X, b1, g1, be1, b2);
    enorm_kernel<<<Bn / 8, 256>>>();
    dist_coarse_kernel<<<Bn / 64, 256, DSM2_TOT>>>();
    rescore_kernel<<<Bn / 4, 128>>>(CB);
    decoder_kernel<<<Bn / 32, 256, DEC_SMEM>>>(CB, b3, g2, be2, b4, X);
    reduce_kernel<<<1, 256>>>();
    final_kernel<<<Bn / 256, 256>>>(out);
}

// round 15
// speedup vs baseline: 1.0688x; 1.0688x over previous
#include <cuda_runtime.h>
#include <cuda_bf16.h>
#include <math.h>
#include <stdint.h>

#define Bn 16384
#define Dn 512
#define Kn 16384
#define Hn 256
#define Zn 128
#define LDK2 136                     // padded row stride in bf16 (272B); bytes 256..259 carry -0.5||c||^2

// ---------------- scratch ----------------
__device__ __align__(16) float g_enc[(size_t)Bn * Zn];
__device__ __align__(16) __nv_bfloat16 g_e0p[(size_t)Bn * LDK2];
__device__ __align__(16) __nv_bfloat16 g_c0p[(size_t)Kn * LDK2];
__device__ float g_negc2[Kn];
__device__ float g_en2[Bn];
__device__ float g_dn2[Bn];
__device__ float g_Rmax2;
__device__ float g_Nmax2;
__device__ float g_smax[Bn];
__device__ float g_cand_val[(size_t)Bn * 48];
__device__ int   g_cand_idx[(size_t)Bn * 48];
__device__ float g_fourth[(size_t)Bn * 16];
__device__ int   g_idx[Bn];
__device__ float g_err[Bn];
__device__ float g_sum;
// W4 pre-packed B-fragments: [s(16)][j(64)][p(2)][lane(32)] of uint2
__device__ __align__(16) uint2 g_W4f[16 * 64 * 2 * 32];
// col-pair packed weights: (W[d][c], W[d][c+half]) as f32x2
__device__ __align__(16) uint64_t g_W1c[512 * 128];   // W1 [512,256], half=128
__device__ __align__(16) uint64_t g_W2c[256 * 64];    // W2 [256,128], half=64
__device__ __align__(16) uint64_t g_W3c[128 * 128];   // W3 [128,256], half=128

// ---------------- helpers ----------------
__device__ __forceinline__ uint32_t smem_u32(const void* p) {
    uint32_t a;
    asm("{ .reg .u64 t; cvta.to.shared.u64 t, %1; cvt.u32.u64 %0, t; }" : "=r"(a) : "l"(p));
    return a;
}
__device__ __forceinline__ void ldsm_x4(uint32_t r[4], uint32_t addr) {
    asm volatile("ldmatrix.sync.aligned.m8n8.x4.shared.b16 {%0,%1,%2,%3}, [%4];"
        : "=r"(r[0]), "=r"(r[1]), "=r"(r[2]), "=r"(r[3]) : "r"(addr));
}
__device__ __forceinline__ void mma_bf16(float d[4], const uint32_t a[4], const uint32_t b[2]) {
    asm volatile("mma.sync.aligned.m16n8k16.row.col.f32.bf16.bf16.f32 "
        "{%0,%1,%2,%3}, {%4,%5,%6,%7}, {%8,%9}, {%0,%1,%2,%3};"
        : "+f"(d[0]), "+f"(d[1]), "+f"(d[2]), "+f"(d[3])
        : "r"(a[0]), "r"(a[1]), "r"(a[2]), "r"(a[3]), "r"(b[0]), "r"(b[1]));
}
__device__ __forceinline__ uint32_t pack_bf16(float a, float b) {
    __nv_bfloat162 t = __floats2bfloat162_rn(a, b);
    return *(uint32_t*)&t;
}
__device__ __forceinline__ uint64_t packf2(float a, float b) {
    uint64_t r;
    asm("mov.b64 %0, {%1, %2};" : "=l"(r) : "f"(a), "f"(b));
    return r;
}
__device__ __forceinline__ void fma_f32x2(uint64_t& d, uint64_t a, uint64_t b) {
    asm("fma.rn.f32x2 %0, %1, %2, %0;" : "+l"(d) : "l"(a), "l"(b));
}
__device__ __forceinline__ void unpackf2(float& lo, float& hi, uint64_t v) {
    asm("mov.b64 {%0, %1}, %2;" : "=f"(lo), "=f"(hi) : "l"(v));
}
__device__ __forceinline__ uint64_t packu64(float a, float b) {
    return ((uint64_t)__float_as_uint(b) << 32) | (uint64_t)__float_as_uint(a);
}
__device__ __forceinline__ void bulk_g2s(uint32_t dst, const void* src, uint32_t bytes, uint32_t mbar) {
    asm volatile("cp.async.bulk.shared::cluster.global.mbarrier::complete_tx::bytes [%0], [%1], %2, [%3];"
        :: "r"(dst), "l"(src), "r"(bytes), "r"(mbar) : "memory");
}
#define MBAR_INIT(mb, c) \
    asm volatile("mbarrier.init.shared.b64 [%0], %1;" :: "r"((uint32_t)(mb)), "r"((uint32_t)(c)) : "memory")
#define MBAR_EXPECT_TX(mb, n) \
    asm volatile("mbarrier.arrive.expect_tx.shared.b64 _, [%0], %1;" :: "r"((uint32_t)(mb)), "r"((uint32_t)(n)) : "memory")
#define MBAR_ARRIVE(mb) \
    asm volatile("mbarrier.arrive.shared.b64 _, [%0];" :: "r"((uint32_t)(mb)) : "memory")
#define MBAR_WAIT(mb, par) do { \
    uint32_t _m = (uint32_t)(mb); uint32_t _p = (uint32_t)(par); uint32_t _d; \
    asm volatile("{\n\t.reg .pred p;\n\t" \
        "mbarrier.try_wait.parity.acquire.cta.shared::cta.b64 p, [%1], %2;\n\t" \
        "selp.b32 %0, 1, 0, p;\n\t}" : "=r"(_d) : "r"(_m), "r"(_p) : "memory"); \
    if (!_d) { \
        asm volatile("{\n\t.reg .pred P1;\n\t" \
            "WL_%=:\n\t" \
            "mbarrier.try_wait.parity.acquire.cta.shared::cta.b64 P1, [%0], %1, 0x989680;\n\t" \
            "@P1 bra.uni WD_%=;\n\tbra.uni WL_%=;\n\tWD_%=:\n\t}" \
            :: "r"(_m), "r"(_p) : "memory"); \
    } } while (0)

// ---------------- weight col-pair prep (W1, W2, W3) ----------------
__global__ void wprep_kernel(const float* __restrict__ W1,
                             const float* __restrict__ W2,
                             const float* __restrict__ W3)
{
    int i = blockIdx.x * 256 + threadIdx.x;   // 98304 total
    if (i < 65536) {
        int d = i >> 7, c = i & 127;
        g_W1c[i] = packu64(W1[d * Hn + c], W1[d * Hn + c + 128]);
    } else if (i < 81920) {
        int j = i - 65536;
        int d = j >> 6, c = j & 63;
        g_W2c[j] = packu64(W2[d * Zn + c], W2[d * Zn + c + 64]);
    } else {
        int j = i - 81920;
        int d = j >> 7, c = j & 127;
        g_W3c[j] = packu64(W3[d * Hn + c], W3[d * Hn + c + 128]);
    }
}

// ---------------- encoder (f32x2 col-pair GEMMs, pre-packed weights) ----------------
__global__ void encoder_kernel(const float* __restrict__ X,
                               const float* __restrict__ b1,
                               const float* __restrict__ g1, const float* __restrict__ be1,
                               const float* __restrict__ b2)
{
    extern __shared__ float sm[];
    float* Xs = sm;
    float* Hs = sm + 32 * Dn;
    const int tid = threadIdx.x;
    const int row0 = blockIdx.x * 32;

    {
        const float4* Xg = (const float4*)(X + (size_t)row0 * Dn);
        float4* Xs4 = (float4*)Xs;
        for (int i = tid; i < 32 * Dn / 4; i += 256) Xs4[i] = Xg[i];
    }
    __syncthreads();

    // GEMM1: thread -> cols (c, c+128), rows rbase..rbase+15, packed f32x2
    {
        const float4* Xs4 = (const float4*)Xs;
        const int c = tid & 127;
        const int rbase = (tid >> 7) * 16;
        uint64_t acc2[16];
#pragma unroll
        for (int r = 0; r < 16; ++r) acc2[r] = 0ull;
        for (int d = 0; d < Dn; d += 4) {
            uint64_t wp[4];
#pragma unroll
            for (int j = 0; j < 4; ++j)
                wp[j] = g_W1c[(d + j) * 128 + c];
#pragma unroll
            for (int r = 0; r < 16; ++r) {
                float4 x = Xs4[((rbase + r) * Dn + d) >> 2];
                fma_f32x2(acc2[r], packf2(x.x, x.x), wp[0]);
                fma_f32x2(acc2[r], packf2(x.y, x.y), wp[1]);
                fma_f32x2(acc2[r], packf2(x.z, x.z), wp[2]);
                fma_f32x2(acc2[r], packf2(x.w, x.w), wp[3]);
            }
        }
        float bba = b1[c], bbb = b1[c + 128];
#pragma unroll
        for (int r = 0; r < 16; ++r) {
            float lo, hi;
            unpackf2(lo, hi, acc2[r]);
            Hs[(rbase + r) * Hn + c]       = lo + bba;
            Hs[(rbase + r) * Hn + c + 128] = hi + bbb;
        }
    }
    __syncthreads();

    // LN + GELU
    {
        const int warp = tid >> 5, lane = tid & 31;
        for (int rr = 0; rr < 4; ++rr) {
            int r = warp + rr * 8;
            float s = 0.f, s2 = 0.f;
#pragma unroll
            for (int j = 0; j < 8; ++j) {
                float v = Hs[r * Hn + lane + j * 32];
                s += v; s2 += v * v;
            }
#pragma unroll
            for (int o = 16; o > 0; o >>= 1) {
                s  += __shfl_xor_sync(0xffffffff, s,  o);
                s2 += __shfl_xor_sync(0xffffffff, s2, o);
            }
            float mu  = s * (1.f / Hn);
            float var = s2 * (1.f / Hn) - mu * mu;
            float inv = rsqrtf(var + 1e-5f);
#pragma unroll
            for (int j = 0; j < 8; ++j) {
                int c = lane + j * 32;
                float v = (Hs[r * Hn + c] - mu) * inv * g1[c] + be1[c];
                Hs[r * Hn + c] = 0.5f * v * (1.f + erff(v * 0.70710678118654752f));
            }
        }
    }
    __syncthreads();

    // GEMM2: thread -> cols (c2, c2+64), rows rbase..rbase+7, packed f32x2
    {
        const float4* Hs4 = (const float4*)Hs;
        const int c2 = tid & 63;
        const int rbase = (tid >> 6) * 8;
        uint64_t acc2[8];
#pragma unroll
        for (int r = 0; r < 8; ++r) acc2[r] = 0ull;
        for (int d = 0; d < Hn; d += 4) {
            uint64_t wp[4];
#pragma unroll
            for (int j = 0; j < 4; ++j)
                wp[j] = g_W2c[(d + j) * 64 + c2];
#pragma unroll
            for (int r = 0; r < 8; ++r) {
                float4 h = Hs4[((rbase + r) * Hn + d) >> 2];
                fma_f32x2(acc2[r], packf2(h.x, h.x), wp[0]);
                fma_f32x2(acc2[r], packf2(h.y, h.y), wp[1]);
                fma_f32x2(acc2[r], packf2(h.z, h.z), wp[2]);
                fma_f32x2(acc2[r], packf2(h.w, h.w), wp[3]);
            }
        }
        float bba = b2[c2], bbb = b2[c2 + 64];
#pragma unroll
        for (int r = 0; r < 8; ++r) {
            float lo, hi;
            unpackf2(lo, hi, acc2[r]);
            g_enc[(size_t)(row0 + rbase + r) * Zn + c2]      = lo + bba;
            g_enc[(size_t)(row0 + rbase + r) * Zn + c2 + 64] = hi + bbb;
        }
    }
}

// ---------------- per-row e0 (padded) + norms ----------------
__global__ void enorm_kernel()
{
    int gw = (blockIdx.x * 256 + threadIdx.x) >> 5;
    int lane = threadIdx.x & 31;
    const float4 e4 = ((const float4*)(g_enc + (size_t)gw * 128))[lane];
    float e0x = __bfloat162float(__float2bfloat16(e4.x));
    float e0y = __bfloat162float(__float2bfloat16(e4.y));
    float e0z = __bfloat162float(__float2bfloat16(e4.z));
    float e0w = __bfloat162float(__float2bfloat16(e4.w));
    *(uint2*)(g_e0p + (size_t)gw * LDK2 + lane * 4) =
        make_uint2(pack_bf16(e4.x, e4.y), pack_bf16(e4.z, e4.w));
    float en2 = e4.x*e4.x + e4.y*e4.y + e4.z*e4.z + e4.w*e4.w;
    float dx = e4.x - e0x, dy = e4.y - e0y, dz = e4.z - e0z, dw = e4.w - e0w;
    float dn2 = dx*dx + dy*dy + dz*dz + dw*dw;
#pragma unroll
    for (int o = 16; o > 0; o >>= 1) {
        en2 += __shfl_xor_sync(0xffffffff, en2, o);
        dn2 += __shfl_xor_sync(0xffffffff, dn2, o);
    }
    if (lane == 0) { g_en2[gw] = en2; g_dn2[gw] = dn2; }
}

// ---------------- codebook prep (padded; nc stashed in row padding) ----------------
__global__ void c0split_kernel(const float* __restrict__ C)
{
    int code = (blockIdx.x * 256 + threadIdx.x) >> 5;
    int lane = threadIdx.x & 31;
    const float4 c4 = ((const float4*)(C + (size_t)code * 128))[lane];
    float c0x = __bfloat162float(__float2bfloat16(c4.x));
    float c0y = __bfloat162float(__float2bfloat16(c4.y));
    float c0z = __bfloat162float(__float2bfloat16(c4.z));
    float c0w = __bfloat162float(__float2bfloat16(c4.w));
    *(uint2*)(g_c0p + (size_t)code * LDK2 + lane * 4) =
        make_uint2(pack_bf16(c4.x, c4.y), pack_bf16(c4.z, c4.w));
    float c2 = c4.x*c4.x + c4.y*c4.y + c4.z*c4.z + c4.w*c4.w;
    float n2 = c0x*c0x + c0y*c0y + c0z*c0z + c0w*c0w;
    float dx = c4.x - c0x, dy = c4.y - c0y, dz = c4.z - c0z, dw = c4.w - c0w;
    float r2 = dx*dx + dy*dy + dz*dz + dw*dw;
#pragma unroll
    for (int o = 16; o > 0; o >>= 1) {
        c2 += __shfl_xor_sync(0xffffffff, c2, o);
        n2 += __shfl_xor_sync(0xffffffff, n2, o);
        r2 += __shfl_xor_sync(0xffffffff, r2, o);
    }
    if (lane == 0) {
        float nc = -0.5f * c2;
        g_negc2[code] = nc;
        *(float*)((char*)g_c0p + (size_t)code * (LDK2 * 2) + 256) = nc;
        atomicMax((int*)&g_Rmax2, __float_as_int(r2));
        atomicMax((int*)&g_Nmax2, __float_as_int(n2));
    }
}

// ---------------- W4 fragment pre-pack (2-way bf16 split, B-frag order) ----------------
__global__ void w4split_kernel(const float* __restrict__ W4)
{
    int i = blockIdx.x * 256 + threadIdx.x;
    int lane = i & 31;
    int p = (i >> 5) & 1;
    int j = (i >> 6) & 63;
    int s = i >> 12;
    int n = j * 8 + (lane >> 2);
    uint32_t regs[2];
#pragma unroll
    for (int r = 0; r < 2; ++r) {
        int k = s * 16 + (lane & 3) * 2 + r * 8;
        float wa = W4[(size_t)k * Dn + n];
        float wb = W4[(size_t)(k + 1) * Dn + n];
        float va, vb;
        if (p == 0) {
            va = __bfloat162float(__float2bfloat16(wa));
            vb = __bfloat162float(__float2bfloat16(wb));
        } else {
            va = wa - __bfloat162float(__float2bfloat16(wa));
            vb = wb - __bfloat162float(__float2bfloat16(wb));
        }
        regs[r] = pack_bf16(va, vb);
    }
    g_W4f[i] = make_uint2(regs[0], regs[1]);
}

// ---------------- coarse distance: mbarrier ring; nc folded into acc init ----------------
#define A_BYTES (64 * LDK2 * 2)
#define TILE_BYTES (128 * LDK2 * 2)
#define SB_A 0
#define SB_B0 A_BYTES
#define SB_MBAR (A_BYTES + 2 * TILE_BYTES)
#define SB_RED (SB_MBAR + 64)
#define DSM2_TOT (SB_RED + 64 * 16 * 4)

__global__ __launch_bounds__(256, 2) void dist_coarse_kernel()
{
    extern __shared__ char smem[];
    float* redsm = (float*)(smem + SB_RED);

    const int tid  = threadIdx.x;
    const int lane = tid & 31;
    const int wid  = tid >> 5;
    const int warp_m = wid >> 2;
    const int warp_n = wid & 3;
    const int row0 = blockIdx.x * 64;

    const uint32_t sbA    = smem_u32(smem) + SB_A;
    const uint32_t sbB0   = smem_u32(smem) + SB_B0;
    const uint32_t mbA    = smem_u32(smem) + SB_MBAR;
    const uint32_t mbF0   = mbA + 8;
    const uint32_t mbF1   = mbA + 16;
    const uint32_t mbE0   = mbA + 24;
    const uint32_t mbE1   = mbA + 32;

    if (tid == 0) {
        MBAR_INIT(mbA, 1);
        MBAR_INIT(mbF0, 1);
        MBAR_INIT(mbF1, 1);
        MBAR_INIT(mbE0, 8);
        MBAR_INIT(mbE1, 8);
    }
    __syncthreads();

    if (tid == 0) {
        MBAR_EXPECT_TX(mbA, A_BYTES);
        bulk_g2s(sbA, g_e0p + (size_t)row0 * LDK2, A_BYTES, mbA);
        MBAR_EXPECT_TX(mbF0, TILE_BYTES);
        bulk_g2s(sbB0, g_c0p, TILE_BYTES, mbF0);
    }

    uint32_t a_addr[2];
#pragma unroll
    for (int mi = 0; mi < 2; ++mi)
        a_addr[mi] = sbA + ((warp_m * 32 + mi * 16 + (lane & 15)) * LDK2 + (lane >> 4) * 8) * 2;
    uint32_t b_addr[2];
#pragma unroll
    for (int njp = 0; njp < 2; ++njp)
        b_addr[njp] = sbB0 + ((warp_n * 32 + njp * 16 + (lane & 7) + ((lane >> 4) << 3)) * LDK2
                              + ((lane >> 3) & 1) * 8) * 2;

    float v1[4], v2[4], v3[4], v4[4];
    int   i1[4], i2[4], i3[4];
#pragma unroll
    for (int r = 0; r < 4; ++r) {
        v1[r] = v2[r] = v3[r] = v4[r] = -INFINITY;
        i1[r] = i2[r] = i3[r] = 0;
    }

    const int cq = (lane & 3) * 2;

    MBAR_WAIT(mbA, 0);

    for (int t = 0, kt = 0; t < 128; ++t, kt += 128) {
        const uint32_t bufo = (uint32_t)(t & 1) * TILE_BYTES;

        if (tid == 0 && t < 127) {
            const int tn = t + 1;
            const int bn = tn & 1;
            const int f  = tn >> 1;
            uint32_t mbE = bn ? mbE1 : mbE0;
            uint32_t mbF = bn ? mbF1 : mbF0;
            if (f > 0) MBAR_WAIT(mbE, (f & 1) ^ 1);
            MBAR_EXPECT_TX(mbF, TILE_BYTES);
            bulk_g2s(sbB0 + (uint32_t)bn * TILE_BYTES,
                     g_c0p + (size_t)(kt + 128) * LDK2, TILE_BYTES, mbF);
        }

        MBAR_WAIT((t & 1) ? mbF1 : mbF0, (t >> 1) & 1);

        float nc[8];
#pragma unroll
        for (int nj = 0; nj < 4; ++nj) {
#pragma unroll
            for (int q = 0; q < 2; ++q) {
                asm volatile("ld.shared.f32 %0, [%1];"
                    : "=f"(nc[nj * 2 + q])
                    : "r"(sbB0 + bufo + (uint32_t)(warp_n * 32 + nj * 8 + cq + q) * (LDK2 * 2) + 256));
            }
        }

        float acc[2][4][4];
#pragma unroll
        for (int mi = 0; mi < 2; ++mi)
#pragma unroll
            for (int nj = 0; nj < 4; ++nj)
#pragma unroll
                for (int k = 0; k < 4; ++k) acc[mi][nj][k] = nc[nj * 2 + (k & 1)];

#pragma unroll
        for (int s = 0; s < 8; ++s) {
            uint32_t af[2][4], bf[2][4];
#pragma unroll
            for (int mi = 0; mi < 2; ++mi) ldsm_x4(af[mi], a_addr[mi] + s * 32);
#pragma unroll
            for (int njp = 0; njp < 2; ++njp) ldsm_x4(bf[njp], b_addr[njp] + bufo + s * 32);
#pragma unroll
            for (int mi = 0; mi < 2; ++mi)
#pragma unroll
                for (int nj = 0; nj < 4; ++nj)
                    mma_bf16(acc[mi][nj], af[mi], bf[nj >> 1] + (nj & 1) * 2);
        }

        if (lane == 0) MBAR_ARRIVE((t & 1) ? mbE1 : mbE0);

#pragma unroll
        for (int mi = 0; mi < 2; ++mi) {
#pragma unroll
            for (int h = 0; h < 2; ++h) {
                const int ri = mi * 2 + h;
                float s0 = acc[mi][0][h * 2];
                float s1 = acc[mi][0][h * 2 + 1];
                float s2 = acc[mi][1][h * 2];
                float s3 = acc[mi][1][h * 2 + 1];
                float s4 = acc[mi][2][h * 2];
                float s5 = acc[mi][2][h * 2 + 1];
                float s6 = acc[mi][3][h * 2];
                float s7 = acc[mi][3][h * 2 + 1];
                float m8 = fmaxf(fmaxf(fmaxf(s0, s1), fmaxf(s2, s3)),
                                 fmaxf(fmaxf(s4, s5), fmaxf(s6, s7)));
                if (m8 > v4[ri]) {
                    float sv[8] = {s0, s1, s2, s3, s4, s5, s6, s7};
#pragma unroll
                    for (int j = 0; j < 8; ++j) {
                        float v = sv[j];
                        if (v > v4[ri]) {
                            int idx = kt + warp_n * 32 + (j >> 1) * 8 + cq + (j & 1);
                            if (v > v1[ri]) {
                                v4[ri] = v3[ri]; v3[ri] = v2[ri]; i3[ri] = i2[ri];
                                v2[ri] = v1[ri]; i2[ri] = i1[ri];
                                v1[ri] = v; i1[ri] = idx;
                            } else if (v > v2[ri]) {
                                v4[ri] = v3[ri]; v3[ri] = v2[ri]; i3[ri] = i2[ri];
                                v2[ri] = v; i2[ri] = idx;
                            } else if (v > v3[ri]) {
                                v4[ri] = v3[ri]; v3[ri] = v; i3[ri] = idx;
                            } else {
                                v4[ri] = v;
                            }
                        }
                    }
                }
            }
        }
    }

    const int slot = warp_n * 4 + (lane & 3);
#pragma unroll
    for (int ri = 0; ri < 4; ++ri) {
        int mi = ri >> 1, h = ri & 1;
        int lrow = warp_m * 32 + mi * 16 + (lane >> 2) + h * 8;
        size_t row = (size_t)(row0 + lrow);
        g_cand_val[row * 48 + slot * 3]     = v1[ri];
        g_cand_idx[row * 48 + slot * 3]     = i1[ri];
        g_cand_val[row * 48 + slot * 3 + 1] = v2[ri];
        g_cand_idx[row * 48 + slot * 3 + 1] = i2[ri];
        g_cand_val[row * 48 + slot * 3 + 2] = v3[ri];
        g_cand_idx[row * 48 + slot * 3 + 2] = i3[ri];
        g_fourth[row * 16 + slot] = v4[ri];
        redsm[lrow * 16 + slot] = v1[ri];
    }
    __syncthreads();
    if (tid < 64) {
        float m = redsm[tid * 16];
#pragma unroll
        for (int w = 1; w < 16; ++w) m = fmaxf(m, redsm[tid * 16 + w]);
        g_smax[row0 + tid] = m;
    }
}

// ---------------- exact rescore (warp per row) ----------------
__global__ void rescore_kernel(const float* __restrict__ CB)
{
    const int r = blockIdx.x * 4 + (threadIdx.x >> 5);
    const int lane = threadIdx.x & 31;

    float delta = sqrtf(g_en2[r]) * sqrtf(g_Rmax2) + sqrtf(g_dn2[r]) * sqrtf(g_Nmax2);
    float thresh = g_smax[r] - 1.05f * delta - 1e-4f;

    float th = (lane < 16) ? g_fourth[(size_t)r * 16 + lane] : -INFINITY;
    bool flag = __ballot_sync(0xffffffff, th >= thresh) != 0;

    const float4 e4 = ((const float4*)(g_enc + (size_t)r * 128))[lane];

    float bs = -INFINITY;
    int bi = 0x7fffffff;

    if (!flag) {
        for (int s = 0; s < 48; ++s) {
            float v = g_cand_val[(size_t)r * 48 + s];
            if (v >= thresh) {
                int idx = g_cand_idx[(size_t)r * 48 + s];
                float4 c4 = ((const float4*)(CB + (size_t)idx * 128))[lane];
                float d = e4.x*c4.x + e4.y*c4.y + e4.z*c4.z + e4.w*c4.w;
#pragma unroll
                for (int o = 16; o > 0; o >>= 1) d += __shfl_xor_sync(0xffffffff, d, o);
                float sx = d + g_negc2[idx];
                if (sx > bs || (sx == bs && idx < bi)) { bs = sx; bi = idx; }
            }
        }
    } else {
        for (int k = 0; k < Kn; ++k) {
            float4 c4 = ((const float4*)(CB + (size_t)k * 128))[lane];
            float d = e4.x*c4.x + e4.y*c4.y + e4.z*c4.z + e4.w*c4.w;
#pragma unroll
            for (int o = 16; o > 0; o >>= 1) d += __shfl_xor_sync(0xffffffff, d, o);
            float sx = d + g_negc2[k];
            if (sx > bs) { bs = sx; bi = k; }
        }
    }
    if (lane == 0) g_idx[r] = bi;
}

// ---------------- decoder: f32x2 col-pair GEMM1 (packed W3), mma GEMM2 ----------------
#define DEC_HS0_OFF (32 * Zn + 32 * Hn)
#define DEC_LDH 264
#define DEC_SMEM (12288 * 4 + 2 * 32 * DEC_LDH * 2 + 32 * 8 * 4)

__global__ void decoder_kernel(const float* __restrict__ C,
                               const float* __restrict__ b3,
                               const float* __restrict__ g2, const float* __restrict__ be2,
                               const float* __restrict__ b4,
                               const float* __restrict__ X)
{
    extern __shared__ float sm[];
    float* Qs = sm;
    float* Hs = sm + 32 * Zn;
    __nv_bfloat16* Hs0 = (__nv_bfloat16*)(sm + DEC_HS0_OFF);
    __nv_bfloat16* Hs1 = Hs0 + 32 * DEC_LDH;
    float* ep = (float*)(Hs1 + 32 * DEC_LDH);
    const int tid = threadIdx.x;
    const int lane = tid & 31;
    const int wid = tid >> 5;
    const int row0 = blockIdx.x * 32;

    for (int i = tid; i < 32 * 32; i += 256) {
        int r = i >> 5, d4 = i & 31;
        int code = g_idx[row0 + r];
        ((float4*)Qs)[r * 32 + d4] = ((const float4*)C)[(size_t)code * 32 + d4];
    }
    __syncthreads();

    // f32x2 GEMM1: thread -> cols (c, c+128), rows rbase..rbase+15
    {
        const float4* Qs4 = (const float4*)Qs;
        const int c = tid & 127;
        const int rbase = (tid >> 7) * 16;
        uint64_t acc2[16];
#pragma unroll
        for (int r = 0; r < 16; ++r) acc2[r] = 0ull;
        for (int d = 0; d < Zn; d += 4) {
            uint64_t wp[4];
#pragma unroll
            for (int j = 0; j < 4; ++j)
                wp[j] = g_W3c[(d + j) * 128 + c];
#pragma unroll
            for (int r = 0; r < 16; ++r) {
                float4 q = Qs4[((rbase + r) * Zn + d) >> 2];
                fma_f32x2(acc2[r], packf2(q.x, q.x), wp[0]);
                fma_f32x2(acc2[r], packf2(q.y, q.y), wp[1]);
                fma_f32x2(acc2[r], packf2(q.z, q.z), wp[2]);
                fma_f32x2(acc2[r], packf2(q.w, q.w), wp[3]);
            }
        }
        float bba = b3[c], bbb = b3[c + 128];
#pragma unroll
        for (int r = 0; r < 16; ++r) {
            float lo, hi;
            unpackf2(lo, hi, acc2[r]);
            Hs[(rbase + r) * Hn + c]       = lo + bba;
            Hs[(rbase + r) * Hn + c + 128] = hi + bbb;
        }
    }
    __syncthreads();

    {
        for (int rr = 0; rr < 4; ++rr) {
            int r = wid + rr * 8;
            float s = 0.f, s2 = 0.f;
#pragma unroll
            for (int j = 0; j < 8; ++j) {
                float v = Hs[r * Hn + lane + j * 32];
                s += v; s2 += v * v;
            }
#pragma unroll
            for (int o = 16; o > 0; o >>= 1) {
                s  += __shfl_xor_sync(0xffffffff, s,  o);
                s2 += __shfl_xor_sync(0xffffffff, s2, o);
            }
            float mu  = s * (1.f / Hn);
            float var = s2 * (1.f / Hn) - mu * mu;
            float inv = rsqrtf(var + 1e-5f);
#pragma unroll
            for (int j = 0; j < 8; ++j) {
                int c = lane + j * 32;
                float v = (Hs[r * Hn + c] - mu) * inv * g2[c] + be2[c];
                Hs[r * Hn + c] = 0.5f * v * (1.f + erff(v * 0.70710678118654752f));
            }
        }
    }
    __syncthreads();

    for (int i = tid; i < 32 * 256; i += 256) {
        int r = i >> 8, c = i & 255;
        float f = Hs[r * Hn + c];
        __nv_bfloat16 h0 = __float2bfloat16(f);
        Hs0[r * DEC_LDH + c] = h0;
        Hs1[r * DEC_LDH + c] = __float2bfloat16(f - __bfloat162float(h0));
    }
    __syncthreads();

    {
        const uint32_t h0b = smem_u32(Hs0);
        const uint32_t h1b = smem_u32(Hs1);
        uint32_t a0_addr[2], a1_addr[2];
#pragma unroll
        for (int mi = 0; mi < 2; ++mi) {
            uint32_t off = (uint32_t)((mi * 16 + (lane & 15)) * DEC_LDH * 2 + (lane >> 4) * 16);
            a0_addr[mi] = h0b + off;
            a1_addr[mi] = h1b + off;
        }

        float e_part[2][2] = {{0.f, 0.f}, {0.f, 0.f}};

#pragma unroll
        for (int h2 = 0; h2 < 2; ++h2) {
            float acc[2][4][4];
#pragma unroll
            for (int mi = 0; mi < 2; ++mi)
#pragma unroll
                for (int nj = 0; nj < 4; ++nj)
#pragma unroll
                    for (int k = 0; k < 4; ++k) acc[mi][nj][k] = 0.f;

            const int j0 = wid * 8 + h2 * 4;
            for (int s = 0; s < 16; ++s) {
                uint32_t a0[2][4], a1[2][4];
#pragma unroll
                for (int mi = 0; mi < 2; ++mi) {
                    ldsm_x4(a0[mi], a0_addr[mi] + s * 32);
                    ldsm_x4(a1[mi], a1_addr[mi] + s * 32);
                }
                uint32_t b0[4][2], b1[4][2];
#pragma unroll
                for (int nj = 0; nj < 4; ++nj) {
                    uint2 v = g_W4f[(size_t)(((s * 64 + j0 + nj) * 2 + 0) * 32 + lane)];
                    b0[nj][0] = v.x; b0[nj][1] = v.y;
                    uint2 w = g_W4f[(size_t)(((s * 64 + j0 + nj) * 2 + 1) * 32 + lane)];
                    b1[nj][0] = w.x; b1[nj][1] = w.y;
                }
#pragma unroll
                for (int mi = 0; mi < 2; ++mi)
#pragma unroll
                    for (int nj = 0; nj < 4; ++nj) {
                        mma_bf16(acc[mi][nj], a0[mi], b0[nj]);
                        mma_bf16(acc[mi][nj], a1[mi], b0[nj]);
                        mma_bf16(acc[mi][nj], a0[mi], b1[nj]);
                    }
            }

#pragma unroll
            for (int nj = 0; nj < 4; ++nj) {
                int col = wid * 64 + h2 * 32 + nj * 8 + (lane & 3) * 2;
                float2 bb = *(const float2*)(b4 + col);
#pragma unroll
                for (int mi = 0; mi < 2; ++mi) {
#pragma unroll
                    for (int hr = 0; hr < 2; ++hr) {
                        int rowg = row0 + mi * 16 + (lane >> 2) + hr * 8;
                        float2 xx = *(const float2*)(X + (size_t)rowg * Dn + col);
                        float d0 = acc[mi][nj][hr * 2]     + bb.x - xx.x;
                        float d1 = acc[mi][nj][hr * 2 + 1] + bb.y - xx.y;
                        e_part[mi][hr] += d0 * d0 + d1 * d1;
                    }
                }
            }
        }

#pragma unroll
        for (int mi = 0; mi < 2; ++mi)
#pragma unroll
            for (int hr = 0; hr < 2; ++hr) {
                float v = e_part[mi][hr];
                v += __shfl_xor_sync(0xffffffff, v, 1);
                v += __shfl_xor_sync(0xffffffff, v, 2);
                if ((lane & 3) == 0)
                    ep[(mi * 16 + (lane >> 2) + hr * 8) * 8 + wid] = v;
            }
    }
    __syncthreads();
    if (tid < 32) {
        float s = 0.f;
#pragma unroll
        for (int w = 0; w < 8; ++w) s += ep[tid * 8 + w];
        g_err[row0 + tid] = s * (1.f / Dn);
    }
}

// ---------------- global mean ----------------
__global__ void reduce_kernel()
{
    __shared__ float s[256];
    int tid = threadIdx.x;
    float a = 0.f;
    for (int i = tid; i < Bn; i += 256) a += g_err[i];
    s[tid] = a;
    __syncthreads();
    for (int o = 128; o > 0; o >>= 1) {
        if (tid < o) s[tid] += s[tid + o];
        __syncthreads();
    }
    if (tid == 0) g_sum = s[0];
}

// ---------------- MDL + output ----------------
__global__ void final_kernel(float* __restrict__ out)
{
    int i = blockIdx.x * 256 + threadIdx.x;
    float scale = g_sum * (1.f / Bn) + 1e-8f;
    float err = g_err[i];
    float eb = (fabsf(err) / scale + logf(2.f * scale)) * 1.4426950408889634f;
    float tb = 14.f + eb;
    out[i]          = err;
    out[Bn + i]     = (Dn * 32.f) / tb;
    out[2 * Bn + i] = tb;
    out[3 * Bn + i] = (float)g_idx[i];
}

// ---------------- launch ----------------
extern "C" void kernel_launch(void* const* d_in, const int* in_sizes, int n_in,
                              void* d_out, int out_size)
{
    const float* X   = (const float*)d_in[0];
    const float* W1  = (const float*)d_in[1];
    const float* b1  = (const float*)d_in[2];
    const float* g1  = (const float*)d_in[3];
    const float* be1 = (const float*)d_in[4];
    const float* W2  = (const float*)d_in[5];
    const float* b2  = (const float*)d_in[6];
    const float* CB  = (const float*)d_in[7];
    const float* W3  = (const float*)d_in[8];
    const float* b3  = (const float*)d_in[9];
    const float* g2  = (const float*)d_in[10];
    const float* be2 = (const float*)d_in[11];
    const float* W4  = (const float*)d_in[12];
    const float* b4  = (const float*)d_in[13];
    float* out = (float*)d_out;

    cudaFuncSetAttribute(encoder_kernel,     cudaFuncAttributeMaxDynamicSharedMemorySize, 98304);
    cudaFuncSetAttribute(dist_coarse_kernel, cudaFuncAttributeMaxDynamicSharedMemorySize, DSM2_TOT);
    cudaFuncSetAttribute(decoder_kernel,     cudaFuncAttributeMaxDynamicSharedMemorySize, DEC_SMEM);

    wprep_kernel<<<384, 256>>>(W1, W2, W3);
    c0split_kernel<<<Kn / 8, 256>>>(CB);
    w4split_kernel<<<256, 256>>>(W4);
    encoder_kernel<<<Bn / 32, 256, 98304>>>(X, b1, g1, be1, b2);
    enorm_kernel<<<Bn / 8, 256>>>();
    dist_coarse_kernel<<<Bn / 64, 256, DSM2_TOT>>>();
    rescore_kernel<<<Bn / 4, 128>>>(CB);
    decoder_kernel<<<Bn / 32, 256, DEC_SMEM>>>(CB, b3, g2, be2, b4, X);
    reduce_kernel<<<1, 256>>>();
    final_kernel<<<Bn / 256, 256>>>(out);
}

// round 16
// speedup vs baseline: 1.0821x; 1.0124x over previous
#include <cuda_runtime.h>
#include <cuda_bf16.h>
#include <math.h>
#include <stdint.h>

#define Bn 16384
#define Dn 512
#define Kn 16384
#define Hn 256
#define Zn 128
#define LDK2 136                     // padded row stride in bf16 (272B); bytes 256..259 carry -0.5||c||^2

// ---------------- scratch ----------------
__device__ __align__(16) float g_enc[(size_t)Bn * Zn];
__device__ __align__(16) __nv_bfloat16 g_e0p[(size_t)Bn * LDK2];
__device__ __align__(16) __nv_bfloat16 g_c0p[(size_t)Kn * LDK2];
__device__ float g_negc2[Kn];
__device__ float g_en2[Bn];
__device__ float g_dn2[Bn];
__device__ float g_Rmax2;
__device__ float g_Nmax2;
__device__ float g_smax[Bn];
__device__ float g_cand_val[(size_t)Bn * 48];
__device__ int   g_cand_idx[(size_t)Bn * 48];
__device__ float g_fourth[(size_t)Bn * 16];
__device__ int   g_idx[Bn];
__device__ float g_err[Bn];
__device__ float g_sum;
// W4 pre-packed B-fragments: [s(16)][j(64)][p(2)][lane(32)] of uint2
__device__ __align__(16) uint2 g_W4f[16 * 64 * 2 * 32];

// ---------------- helpers ----------------
__device__ __forceinline__ uint32_t smem_u32(const void* p) {
    uint32_t a;
    asm("{ .reg .u64 t; cvta.to.shared.u64 t, %1; cvt.u32.u64 %0, t; }" : "=r"(a) : "l"(p));
    return a;
}
__device__ __forceinline__ void ldsm_x4(uint32_t r[4], uint32_t addr) {
    asm volatile("ldmatrix.sync.aligned.m8n8.x4.shared.b16 {%0,%1,%2,%3}, [%4];"
        : "=r"(r[0]), "=r"(r[1]), "=r"(r[2]), "=r"(r[3]) : "r"(addr));
}
__device__ __forceinline__ void mma_bf16(float d[4], const uint32_t a[4], const uint32_t b[2]) {
    asm volatile("mma.sync.aligned.m16n8k16.row.col.f32.bf16.bf16.f32 "
        "{%0,%1,%2,%3}, {%4,%5,%6,%7}, {%8,%9}, {%0,%1,%2,%3};"
        : "+f"(d[0]), "+f"(d[1]), "+f"(d[2]), "+f"(d[3])
        : "r"(a[0]), "r"(a[1]), "r"(a[2]), "r"(a[3]), "r"(b[0]), "r"(b[1]));
}
__device__ __forceinline__ uint32_t pack_bf16(float a, float b) {
    __nv_bfloat162 t = __floats2bfloat162_rn(a, b);
    return *(uint32_t*)&t;
}
// packed f32x2 helpers (PTX >= 8.6, sm_100+ base ISA)
__device__ __forceinline__ uint64_t packf2(float a, float b) {
    uint64_t r;
    asm("mov.b64 %0, {%1, %2};" : "=l"(r) : "f"(a), "f"(b));
    return r;
}
__device__ __forceinline__ void fma_f32x2(uint64_t& d, uint64_t a, uint64_t b) {
    asm("fma.rn.f32x2 %0, %1, %2, %0;" : "+l"(d) : "l"(a), "l"(b));
}
__device__ __forceinline__ void unpackf2(float& lo, float& hi, uint64_t v) {
    asm("mov.b64 {%0, %1}, %2;" : "=f"(lo), "=f"(hi) : "l"(v));
}
__device__ __forceinline__ void bulk_g2s(uint32_t dst, const void* src, uint32_t bytes, uint32_t mbar) {
    asm volatile("cp.async.bulk.shared::cluster.global.mbarrier::complete_tx::bytes [%0], [%1], %2, [%3];"
        :: "r"(dst), "l"(src), "r"(bytes), "r"(mbar) : "memory");
}
#define MBAR_INIT(mb, c) \
    asm volatile("mbarrier.init.shared.b64 [%0], %1;" :: "r"((uint32_t)(mb)), "r"((uint32_t)(c)) : "memory")
#define MBAR_EXPECT_TX(mb, n) \
    asm volatile("mbarrier.arrive.expect_tx.shared.b64 _, [%0], %1;" :: "r"((uint32_t)(mb)), "r"((uint32_t)(n)) : "memory")
#define MBAR_ARRIVE(mb) \
    asm volatile("mbarrier.arrive.shared.b64 _, [%0];" :: "r"((uint32_t)(mb)) : "memory")
#define MBAR_WAIT(mb, par) do { \
    uint32_t _m = (uint32_t)(mb); uint32_t _p = (uint32_t)(par); uint32_t _d; \
    asm volatile("{\n\t.reg .pred p;\n\t" \
        "mbarrier.try_wait.parity.acquire.cta.shared::cta.b64 p, [%1], %2;\n\t" \
        "selp.b32 %0, 1, 0, p;\n\t}" : "=r"(_d) : "r"(_m), "r"(_p) : "memory"); \
    if (!_d) { \
        asm volatile("{\n\t.reg .pred P1;\n\t" \
            "WL_%=:\n\t" \
            "mbarrier.try_wait.parity.acquire.cta.shared::cta.b64 P1, [%0], %1, 0x989680;\n\t" \
            "@P1 bra.uni WD_%=;\n\tbra.uni WL_%=;\n\tWD_%=:\n\t}" \
            :: "r"(_m), "r"(_p) : "memory"); \
    } } while (0)

// ---------------- encoder (R13 f32x2 GEMMs) + fused e0/norm epilogue ----------------
__global__ void encoder_kernel(const float* __restrict__ X,
                               const float* __restrict__ W1, const float* __restrict__ b1,
                               const float* __restrict__ g1, const float* __restrict__ be1,
                               const float* __restrict__ W2, const float* __restrict__ b2)
{
    extern __shared__ float sm[];
    float* Xs = sm;
    float* Hs = sm + 32 * Dn;
    const int tid = threadIdx.x;
    const int row0 = blockIdx.x * 32;

    {
        const float4* Xg = (const float4*)(X + (size_t)row0 * Dn);
        float4* Xs4 = (float4*)Xs;
        for (int i = tid; i < 32 * Dn / 4; i += 256) Xs4[i] = Xg[i];
    }
    __syncthreads();

    // GEMM1: thread -> cols (c, c+128), rows rbase..rbase+15, packed f32x2
    {
        const float4* Xs4 = (const float4*)Xs;
        const int c = tid & 127;
        const int rbase = (tid >> 7) * 16;
        uint64_t acc2[16];
#pragma unroll
        for (int r = 0; r < 16; ++r) acc2[r] = 0ull;
        for (int d = 0; d < Dn; d += 4) {
            uint64_t wp[4];
#pragma unroll
            for (int j = 0; j < 4; ++j)
                wp[j] = packf2(W1[(d + j) * Hn + c], W1[(d + j) * Hn + c + 128]);
#pragma unroll
            for (int r = 0; r < 16; ++r) {
                float4 x = Xs4[((rbase + r) * Dn + d) >> 2];
                fma_f32x2(acc2[r], packf2(x.x, x.x), wp[0]);
                fma_f32x2(acc2[r], packf2(x.y, x.y), wp[1]);
                fma_f32x2(acc2[r], packf2(x.z, x.z), wp[2]);
                fma_f32x2(acc2[r], packf2(x.w, x.w), wp[3]);
            }
        }
        float bba = b1[c], bbb = b1[c + 128];
#pragma unroll
        for (int r = 0; r < 16; ++r) {
            float lo, hi;
            unpackf2(lo, hi, acc2[r]);
            Hs[(rbase + r) * Hn + c]       = lo + bba;
            Hs[(rbase + r) * Hn + c + 128] = hi + bbb;
        }
    }
    __syncthreads();

    // LN + GELU
    {
        const int warp = tid >> 5, lane = tid & 31;
        for (int rr = 0; rr < 4; ++rr) {
            int r = warp + rr * 8;
            float s = 0.f, s2 = 0.f;
#pragma unroll
            for (int j = 0; j < 8; ++j) {
                float v = Hs[r * Hn + lane + j * 32];
                s += v; s2 += v * v;
            }
#pragma unroll
            for (int o = 16; o > 0; o >>= 1) {
                s  += __shfl_xor_sync(0xffffffff, s,  o);
                s2 += __shfl_xor_sync(0xffffffff, s2, o);
            }
            float mu  = s * (1.f / Hn);
            float var = s2 * (1.f / Hn) - mu * mu;
            float inv = rsqrtf(var + 1e-5f);
#pragma unroll
            for (int j = 0; j < 8; ++j) {
                int c = lane + j * 32;
                float v = (Hs[r * Hn + c] - mu) * inv * g1[c] + be1[c];
                Hs[r * Hn + c] = 0.5f * v * (1.f + erff(v * 0.70710678118654752f));
            }
        }
    }
    __syncthreads();

    // GEMM2: thread -> cols (c2, c2+64), rows rbase..rbase+7, packed f32x2
    // fused: write g_enc + bf16 g_e0p + row-norm partials (replaces enorm_kernel)
    {
        const float4* Hs4 = (const float4*)Hs;
        const int c2 = tid & 63;
        const int rbase = (tid >> 6) * 8;
        uint64_t acc2[8];
#pragma unroll
        for (int r = 0; r < 8; ++r) acc2[r] = 0ull;
        for (int d = 0; d < Hn; d += 4) {
            uint64_t wp[4];
#pragma unroll
            for (int j = 0; j < 4; ++j)
                wp[j] = packf2(W2[(d + j) * Zn + c2], W2[(d + j) * Zn + c2 + 64]);
#pragma unroll
            for (int r = 0; r < 8; ++r) {
                float4 h = Hs4[((rbase + r) * Hn + d) >> 2];
                fma_f32x2(acc2[r], packf2(h.x, h.x), wp[0]);
                fma_f32x2(acc2[r], packf2(h.y, h.y), wp[1]);
                fma_f32x2(acc2[r], packf2(h.z, h.z), wp[2]);
                fma_f32x2(acc2[r], packf2(h.w, h.w), wp[3]);
            }
        }
        float bba = b2[c2], bbb = b2[c2 + 64];
        float pen[8], pdn[8];
#pragma unroll
        for (int r = 0; r < 8; ++r) {
            float lo, hi;
            unpackf2(lo, hi, acc2[r]);
            float va = lo + bba;
            float vb = hi + bbb;
            size_t grow = (size_t)(row0 + rbase + r);
            g_enc[grow * Zn + c2]      = va;
            g_enc[grow * Zn + c2 + 64] = vb;
            __nv_bfloat16 ba = __float2bfloat16(va);
            __nv_bfloat16 bb16 = __float2bfloat16(vb);
            g_e0p[grow * LDK2 + c2]      = ba;
            g_e0p[grow * LDK2 + c2 + 64] = bb16;
            float fa = __bfloat162float(ba), fb = __bfloat162float(bb16);
            float da = va - fa, db = vb - fb;
            pen[r] = va * va + vb * vb;
            pdn[r] = da * da + db * db;
        }
        // reduce across the 64 threads (2 warps) that own each row
        const int warp = tid >> 5, lane = tid & 31;
        float* epn = Xs;          // [32 rows][2 warps]
        float* edn = Xs + 64;
#pragma unroll
        for (int r = 0; r < 8; ++r) {
            float a = pen[r], bsum = pdn[r];
#pragma unroll
            for (int o = 16; o > 0; o >>= 1) {
                a    += __shfl_xor_sync(0xffffffff, a,    o);
                bsum += __shfl_xor_sync(0xffffffff, bsum, o);
            }
            if (lane == 0) {
                epn[(rbase + r) * 2 + (warp & 1)] = a;
                edn[(rbase + r) * 2 + (warp & 1)] = bsum;
            }
        }
        __syncthreads();
        if (tid < 32) {
            g_en2[row0 + tid] = epn[tid * 2] + epn[tid * 2 + 1];
            g_dn2[row0 + tid] = edn[tid * 2] + edn[tid * 2 + 1];
        }
    }
}

// ---------------- codebook prep (padded; nc stashed in row padding) ----------------
__global__ void c0split_kernel(const float* __restrict__ C)
{
    int code = (blockIdx.x * 256 + threadIdx.x) >> 5;
    int lane = threadIdx.x & 31;
    const float4 c4 = ((const float4*)(C + (size_t)code * 128))[lane];
    float c0x = __bfloat162float(__float2bfloat16(c4.x));
    float c0y = __bfloat162float(__float2bfloat16(c4.y));
    float c0z = __bfloat162float(__float2bfloat16(c4.z));
    float c0w = __bfloat162float(__float2bfloat16(c4.w));
    *(uint2*)(g_c0p + (size_t)code * LDK2 + lane * 4) =
        make_uint2(pack_bf16(c4.x, c4.y), pack_bf16(c4.z, c4.w));
    float c2 = c4.x*c4.x + c4.y*c4.y + c4.z*c4.z + c4.w*c4.w;
    float n2 = c0x*c0x + c0y*c0y + c0z*c0z + c0w*c0w;
    float dx = c4.x - c0x, dy = c4.y - c0y, dz = c4.z - c0z, dw = c4.w - c0w;
    float r2 = dx*dx + dy*dy + dz*dz + dw*dw;
#pragma unroll
    for (int o = 16; o > 0; o >>= 1) {
        c2 += __shfl_xor_sync(0xffffffff, c2, o);
        n2 += __shfl_xor_sync(0xffffffff, n2, o);
        r2 += __shfl_xor_sync(0xffffffff, r2, o);
    }
    if (lane == 0) {
        float nc = -0.5f * c2;
        g_negc2[code] = nc;
        *(float*)((char*)g_c0p + (size_t)code * (LDK2 * 2) + 256) = nc;
        atomicMax((int*)&g_Rmax2, __float_as_int(r2));
        atomicMax((int*)&g_Nmax2, __float_as_int(n2));
    }
}

// ---------------- W4 fragment pre-pack (2-way bf16 split, B-frag order) ----------------
__global__ void w4split_kernel(const float* __restrict__ W4)
{
    int i = blockIdx.x * 256 + threadIdx.x;
    int lane = i & 31;
    int p = (i >> 5) & 1;
    int j = (i >> 6) & 63;
    int s = i >> 12;
    int n = j * 8 + (lane >> 2);
    uint32_t regs[2];
#pragma unroll
    for (int r = 0; r < 2; ++r) {
        int k = s * 16 + (lane & 3) * 2 + r * 8;
        float wa = W4[(size_t)k * Dn + n];
        float wb = W4[(size_t)(k + 1) * Dn + n];
        float va, vb;
        if (p == 0) {
            va = __bfloat162float(__float2bfloat16(wa));
            vb = __bfloat162float(__float2bfloat16(wb));
        } else {
            va = wa - __bfloat162float(__float2bfloat16(wa));
            vb = wb - __bfloat162float(__float2bfloat16(wb));
        }
        regs[r] = pack_bf16(va, vb);
    }
    g_W4f[i] = make_uint2(regs[0], regs[1]);
}

// ---------------- coarse distance: mbarrier ring; nc folded into acc init ----------------
#define A_BYTES (64 * LDK2 * 2)
#define TILE_BYTES (128 * LDK2 * 2)
#define SB_A 0
#define SB_B0 A_BYTES
#define SB_MBAR (A_BYTES + 2 * TILE_BYTES)
#define SB_RED (SB_MBAR + 64)
#define DSM2_TOT (SB_RED + 64 * 16 * 4)

__global__ __launch_bounds__(256, 2) void dist_coarse_kernel()
{
    extern __shared__ char smem[];
    float* redsm = (float*)(smem + SB_RED);

    const int tid  = threadIdx.x;
    const int lane = tid & 31;
    const int wid  = tid >> 5;
    const int warp_m = wid >> 2;
    const int warp_n = wid & 3;
    const int row0 = blockIdx.x * 64;

    const uint32_t sbA    = smem_u32(smem) + SB_A;
    const uint32_t sbB0   = smem_u32(smem) + SB_B0;
    const uint32_t mbA    = smem_u32(smem) + SB_MBAR;
    const uint32_t mbF0   = mbA + 8;
    const uint32_t mbF1   = mbA + 16;
    const uint32_t mbE0   = mbA + 24;
    const uint32_t mbE1   = mbA + 32;

    if (tid == 0) {
        MBAR_INIT(mbA, 1);
        MBAR_INIT(mbF0, 1);
        MBAR_INIT(mbF1, 1);
        MBAR_INIT(mbE0, 8);
        MBAR_INIT(mbE1, 8);
    }
    __syncthreads();

    if (tid == 0) {
        MBAR_EXPECT_TX(mbA, A_BYTES);
        bulk_g2s(sbA, g_e0p + (size_t)row0 * LDK2, A_BYTES, mbA);
        MBAR_EXPECT_TX(mbF0, TILE_BYTES);
        bulk_g2s(sbB0, g_c0p, TILE_BYTES, mbF0);
    }

    uint32_t a_addr[2];
#pragma unroll
    for (int mi = 0; mi < 2; ++mi)
        a_addr[mi] = sbA + ((warp_m * 32 + mi * 16 + (lane & 15)) * LDK2 + (lane >> 4) * 8) * 2;
    uint32_t b_addr[2];
#pragma unroll
    for (int njp = 0; njp < 2; ++njp)
        b_addr[njp] = sbB0 + ((warp_n * 32 + njp * 16 + (lane & 7) + ((lane >> 4) << 3)) * LDK2
                              + ((lane >> 3) & 1) * 8) * 2;

    float v1[4], v2[4], v3[4], v4[4];
    int   i1[4], i2[4], i3[4];
#pragma unroll
    for (int r = 0; r < 4; ++r) {
        v1[r] = v2[r] = v3[r] = v4[r] = -INFINITY;
        i1[r] = i2[r] = i3[r] = 0;
    }

    const int cq = (lane & 3) * 2;

    MBAR_WAIT(mbA, 0);

    for (int t = 0, kt = 0; t < 128; ++t, kt += 128) {
        const uint32_t bufo = (uint32_t)(t & 1) * TILE_BYTES;

        if (tid == 0 && t < 127) {
            const int tn = t + 1;
            const int bn = tn & 1;
            const int f  = tn >> 1;
            uint32_t mbE = bn ? mbE1 : mbE0;
            uint32_t mbF = bn ? mbF1 : mbF0;
            if (f > 0) MBAR_WAIT(mbE, (f & 1) ^ 1);
            MBAR_EXPECT_TX(mbF, TILE_BYTES);
            bulk_g2s(sbB0 + (uint32_t)bn * TILE_BYTES,
                     g_c0p + (size_t)(kt + 128) * LDK2, TILE_BYTES, mbF);
        }

        MBAR_WAIT((t & 1) ? mbF1 : mbF0, (t >> 1) & 1);

        float nc[8];
#pragma unroll
        for (int nj = 0; nj < 4; ++nj) {
#pragma unroll
            for (int q = 0; q < 2; ++q) {
                asm volatile("ld.shared.f32 %0, [%1];"
                    : "=f"(nc[nj * 2 + q])
                    : "r"(sbB0 + bufo + (uint32_t)(warp_n * 32 + nj * 8 + cq + q) * (LDK2 * 2) + 256));
            }
        }

        float acc[2][4][4];
#pragma unroll
        for (int mi = 0; mi < 2; ++mi)
#pragma unroll
            for (int nj = 0; nj < 4; ++nj)
#pragma unroll
                for (int k = 0; k < 4; ++k) acc[mi][nj][k] = nc[nj * 2 + (k & 1)];

#pragma unroll
        for (int s = 0; s < 8; ++s) {
            uint32_t af[2][4], bf[2][4];
#pragma unroll
            for (int mi = 0; mi < 2; ++mi) ldsm_x4(af[mi], a_addr[mi] + s * 32);
#pragma unroll
            for (int njp = 0; njp < 2; ++njp) ldsm_x4(bf[njp], b_addr[njp] + bufo + s * 32);
#pragma unroll
            for (int mi = 0; mi < 2; ++mi)
#pragma unroll
                for (int nj = 0; nj < 4; ++nj)
                    mma_bf16(acc[mi][nj], af[mi], bf[nj >> 1] + (nj & 1) * 2);
        }

        if (lane == 0) MBAR_ARRIVE((t & 1) ? mbE1 : mbE0);

#pragma unroll
        for (int mi = 0; mi < 2; ++mi) {
#pragma unroll
            for (int h = 0; h < 2; ++h) {
                const int ri = mi * 2 + h;
                float s0 = acc[mi][0][h * 2];
                float s1 = acc[mi][0][h * 2 + 1];
                float s2 = acc[mi][1][h * 2];
                float s3 = acc[mi][1][h * 2 + 1];
                float s4 = acc[mi][2][h * 2];
                float s5 = acc[mi][2][h * 2 + 1];
                float s6 = acc[mi][3][h * 2];
                float s7 = acc[mi][3][h * 2 + 1];
                float m8 = fmaxf(fmaxf(fmaxf(s0, s1), fmaxf(s2, s3)),
                                 fmaxf(fmaxf(s4, s5), fmaxf(s6, s7)));
                if (m8 > v4[ri]) {
                    float sv[8] = {s0, s1, s2, s3, s4, s5, s6, s7};
#pragma unroll
                    for (int j = 0; j < 8; ++j) {
                        float v = sv[j];
                        if (v > v4[ri]) {
                            int idx = kt + warp_n * 32 + (j >> 1) * 8 + cq + (j & 1);
                            if (v > v1[ri]) {
                                v4[ri] = v3[ri]; v3[ri] = v2[ri]; i3[ri] = i2[ri];
                                v2[ri] = v1[ri]; i2[ri] = i1[ri];
                                v1[ri] = v; i1[ri] = idx;
                            } else if (v > v2[ri]) {
                                v4[ri] = v3[ri]; v3[ri] = v2[ri]; i3[ri] = i2[ri];
                                v2[ri] = v; i2[ri] = idx;
                            } else if (v > v3[ri]) {
                                v4[ri] = v3[ri]; v3[ri] = v; i3[ri] = idx;
                            } else {
                                v4[ri] = v;
                            }
                        }
                    }
                }
            }
        }
    }

    const int slot = warp_n * 4 + (lane & 3);
#pragma unroll
    for (int ri = 0; ri < 4; ++ri) {
        int mi = ri >> 1, h = ri & 1;
        int lrow = warp_m * 32 + mi * 16 + (lane >> 2) + h * 8;
        size_t row = (size_t)(row0 + lrow);
        g_cand_val[row * 48 + slot * 3]     = v1[ri];
        g_cand_idx[row * 48 + slot * 3]     = i1[ri];
        g_cand_val[row * 48 + slot * 3 + 1] = v2[ri];
        g_cand_idx[row * 48 + slot * 3 + 1] = i2[ri];
        g_cand_val[row * 48 + slot * 3 + 2] = v3[ri];
        g_cand_idx[row * 48 + slot * 3 + 2] = i3[ri];
        g_fourth[row * 16 + slot] = v4[ri];
        redsm[lrow * 16 + slot] = v1[ri];
    }
    __syncthreads();
    if (tid < 64) {
        float m = redsm[tid * 16];
#pragma unroll
        for (int w = 1; w < 16; ++w) m = fmaxf(m, redsm[tid * 16 + w]);
        g_smax[row0 + tid] = m;
    }
}

// ---------------- exact rescore (warp per row) ----------------
__global__ void rescore_kernel(const float* __restrict__ CB)
{
    const int r = blockIdx.x * 4 + (threadIdx.x >> 5);
    const int lane = threadIdx.x & 31;

    float delta = sqrtf(g_en2[r]) * sqrtf(g_Rmax2) + sqrtf(g_dn2[r]) * sqrtf(g_Nmax2);
    float thresh = g_smax[r] - 1.05f * delta - 1e-4f;

    float th = (lane < 16) ? g_fourth[(size_t)r * 16 + lane] : -INFINITY;
    bool flag = __ballot_sync(0xffffffff, th >= thresh) != 0;

    const float4 e4 = ((const float4*)(g_enc + (size_t)r * 128))[lane];

    float bs = -INFINITY;
    int bi = 0x7fffffff;

    if (!flag) {
        for (int s = 0; s < 48; ++s) {
            float v = g_cand_val[(size_t)r * 48 + s];
            if (v >= thresh) {
                int idx = g_cand_idx[(size_t)r * 48 + s];
                float4 c4 = ((const float4*)(CB + (size_t)idx * 128))[lane];
                float d = e4.x*c4.x + e4.y*c4.y + e4.z*c4.z + e4.w*c4.w;
#pragma unroll
                for (int o = 16; o > 0; o >>= 1) d += __shfl_xor_sync(0xffffffff, d, o);
                float sx = d + g_negc2[idx];
                if (sx > bs || (sx == bs && idx < bi)) { bs = sx; bi = idx; }
            }
        }
    } else {
        for (int k = 0; k < Kn; ++k) {
            float4 c4 = ((const float4*)(CB + (size_t)k * 128))[lane];
            float d = e4.x*c4.x + e4.y*c4.y + e4.z*c4.z + e4.w*c4.w;
#pragma unroll
            for (int o = 16; o > 0; o >>= 1) d += __shfl_xor_sync(0xffffffff, d, o);
            float sx = d + g_negc2[k];
            if (sx > bs) { bs = sx; bi = k; }
        }
    }
    if (lane == 0) g_idx[r] = bi;
}

// ---------------- decoder: f32x2 GEMM1 (inline W3 pack), mma GEMM2 ----------------
#define DEC_HS0_OFF (32 * Zn + 32 * Hn)
#define DEC_LDH 264
#define DEC_SMEM (12288 * 4 + 2 * 32 * DEC_LDH * 2 + 32 * 8 * 4)

__global__ void decoder_kernel(const float* __restrict__ C,
                               const float* __restrict__ W3, const float* __restrict__ b3,
                               const float* __restrict__ g2, const float* __restrict__ be2,
                               const float* __restrict__ b4,
                               const float* __restrict__ X)
{
    extern __shared__ float sm[];
    float* Qs = sm;
    float* Hs = sm + 32 * Zn;
    __nv_bfloat16* Hs0 = (__nv_bfloat16*)(sm + DEC_HS0_OFF);
    __nv_bfloat16* Hs1 = Hs0 + 32 * DEC_LDH;
    float* ep = (float*)(Hs1 + 32 * DEC_LDH);
    const int tid = threadIdx.x;
    const int lane = tid & 31;
    const int wid = tid >> 5;
    const int row0 = blockIdx.x * 32;

    for (int i = tid; i < 32 * 32; i += 256) {
        int r = i >> 5, d4 = i & 31;
        int code = g_idx[row0 + r];
        ((float4*)Qs)[r * 32 + d4] = ((const float4*)C)[(size_t)code * 32 + d4];
    }
    __syncthreads();

    // f32x2 GEMM1: thread -> cols (c, c+128), rows rbase..rbase+15
    {
        const float4* Qs4 = (const float4*)Qs;
        const int c = tid & 127;
        const int rbase = (tid >> 7) * 16;
        uint64_t acc2[16];
#pragma unroll
        for (int r = 0; r < 16; ++r) acc2[r] = 0ull;
        for (int d = 0; d < Zn; d += 4) {
            uint64_t wp[4];
#pragma unroll
            for (int j = 0; j < 4; ++j)
                wp[j] = packf2(W3[(d + j) * Hn + c], W3[(d + j) * Hn + c + 128]);
#pragma unroll
            for (int r = 0; r < 16; ++r) {
                float4 q = Qs4[((rbase + r) * Zn + d) >> 2];
                fma_f32x2(acc2[r], packf2(q.x, q.x), wp[0]);
                fma_f32x2(acc2[r], packf2(q.y, q.y), wp[1]);
                fma_f32x2(acc2[r], packf2(q.z, q.z), wp[2]);
                fma_f32x2(acc2[r], packf2(q.w, q.w), wp[3]);
            }
        }
        float bba = b3[c], bbb = b3[c + 128];
#pragma unroll
        for (int r = 0; r < 16; ++r) {
            float lo, hi;
            unpackf2(lo, hi, acc2[r]);
            Hs[(rbase + r) * Hn + c]       = lo + bba;
            Hs[(rbase + r) * Hn + c + 128] = hi + bbb;
        }
    }
    __syncthreads();

    {
        for (int rr = 0; rr < 4; ++rr) {
            int r = wid + rr * 8;
            float s = 0.f, s2 = 0.f;
#pragma unroll
            for (int j = 0; j < 8; ++j) {
                float v = Hs[r * Hn + lane + j * 32];
                s += v; s2 += v * v;
            }
#pragma unroll
            for (int o = 16; o > 0; o >>= 1) {
                s  += __shfl_xor_sync(0xffffffff, s,  o);
                s2 += __shfl_xor_sync(0xffffffff, s2, o);
            }
            float mu  = s * (1.f / Hn);
            float var = s2 * (1.f / Hn) - mu * mu;
            float inv = rsqrtf(var + 1e-5f);
#pragma unroll
            for (int j = 0; j < 8; ++j) {
                int c = lane + j * 32;
                float v = (Hs[r * Hn + c] - mu) * inv * g2[c] + be2[c];
                Hs[r * Hn + c] = 0.5f * v * (1.f + erff(v * 0.70710678118654752f));
            }
        }
    }
    __syncthreads();

    for (int i = tid; i < 32 * 256; i += 256) {
        int r = i >> 8, c = i & 255;
        float f = Hs[r * Hn + c];
        __nv_bfloat16 h0 = __float2bfloat16(f);
        Hs0[r * DEC_LDH + c] = h0;
        Hs1[r * DEC_LDH + c] = __float2bfloat16(f - __bfloat162float(h0));
    }
    __syncthreads();

    {
        const uint32_t h0b = smem_u32(Hs0);
        const uint32_t h1b = smem_u32(Hs1);
        uint32_t a0_addr[2], a1_addr[2];
#pragma unroll
        for (int mi = 0; mi < 2; ++mi) {
            uint32_t off = (uint32_t)((mi * 16 + (lane & 15)) * DEC_LDH * 2 + (lane >> 4) * 16);
            a0_addr[mi] = h0b + off;
            a1_addr[mi] = h1b + off;
        }

        float e_part[2][2] = {{0.f, 0.f}, {0.f, 0.f}};

#pragma unroll
        for (int h2 = 0; h2 < 2; ++h2) {
            float acc[2][4][4];
#pragma unroll
            for (int mi = 0; mi < 2; ++mi)
#pragma unroll
                for (int nj = 0; nj < 4; ++nj)
#pragma unroll
                    for (int k = 0; k < 4; ++k) acc[mi][nj][k] = 0.f;

            const int j0 = wid * 8 + h2 * 4;
            for (int s = 0; s < 16; ++s) {
                uint32_t a0[2][4], a1[2][4];
#pragma unroll
                for (int mi = 0; mi < 2; ++mi) {
                    ldsm_x4(a0[mi], a0_addr[mi] + s * 32);
                    ldsm_x4(a1[mi], a1_addr[mi] + s * 32);
                }
                uint32_t b0[4][2], b1[4][2];
#pragma unroll
                for (int nj = 0; nj < 4; ++nj) {
                    uint2 v = g_W4f[(size_t)(((s * 64 + j0 + nj) * 2 + 0) * 32 + lane)];
                    b0[nj][0] = v.x; b0[nj][1] = v.y;
                    uint2 w = g_W4f[(size_t)(((s * 64 + j0 + nj) * 2 + 1) * 32 + lane)];
                    b1[nj][0] = w.x; b1[nj][1] = w.y;
                }
#pragma unroll
                for (int mi = 0; mi < 2; ++mi)
#pragma unroll
                    for (int nj = 0; nj < 4; ++nj) {
                        mma_bf16(acc[mi][nj], a0[mi], b0[nj]);
                        mma_bf16(acc[mi][nj], a1[mi], b0[nj]);
                        mma_bf16(acc[mi][nj], a0[mi], b1[nj]);
                    }
            }

#pragma unroll
            for (int nj = 0; nj < 4; ++nj) {
                int col = wid * 64 + h2 * 32 + nj * 8 + (lane & 3) * 2;
                float2 bb = *(const float2*)(b4 + col);
#pragma unroll
                for (int mi = 0; mi < 2; ++mi) {
#pragma unroll
                    for (int hr = 0; hr < 2; ++hr) {
                        int rowg = row0 + mi * 16 + (lane >> 2) + hr * 8;
                        float2 xx = *(const float2*)(X + (size_t)rowg * Dn + col);
                        float d0 = acc[mi][nj][hr * 2]     + bb.x - xx.x;
                        float d1 = acc[mi][nj][hr * 2 + 1] + bb.y - xx.y;
                        e_part[mi][hr] += d0 * d0 + d1 * d1;
                    }
                }
            }
        }

#pragma unroll
        for (int mi = 0; mi < 2; ++mi)
#pragma unroll
            for (int hr = 0; hr < 2; ++hr) {
                float v = e_part[mi][hr];
                v += __shfl_xor_sync(0xffffffff, v, 1);
                v += __shfl_xor_sync(0xffffffff, v, 2);
                if ((lane & 3) == 0)
                    ep[(mi * 16 + (lane >> 2) + hr * 8) * 8 + wid] = v;
            }
    }
    __syncthreads();
    if (tid < 32) {
        float s = 0.f;
#pragma unroll
        for (int w = 0; w < 8; ++w) s += ep[tid * 8 + w];
        g_err[row0 + tid] = s * (1.f / Dn);
    }
}

// ---------------- global mean ----------------
__global__ void reduce_kernel()
{
    __shared__ float s[256];
    int tid = threadIdx.x;
    float a = 0.f;
    for (int i = tid; i < Bn; i += 256) a += g_err[i];
    s[tid] = a;
    __syncthreads();
    for (int o = 128; o > 0; o >>= 1) {
        if (tid < o) s[tid] += s[tid + o];
        __syncthreads();
    }
    if (tid == 0) g_sum = s[0];
}

// ---------------- MDL + output ----------------
__global__ void final_kernel(float* __restrict__ out)
{
    int i = blockIdx.x * 256 + threadIdx.x;
    float scale = g_sum * (1.f / Bn) + 1e-8f;
    float err = g_err[i];
    float eb = (fabsf(err) / scale + logf(2.f * scale)) * 1.4426950408889634f;
    float tb = 14.f + eb;
    out[i]          = err;
    out[Bn + i]     = (Dn * 32.f) / tb;
    out[2 * Bn + i] = tb;
    out[3 * Bn + i] = (float)g_idx[i];
}

// ---------------- launch ----------------
extern "C" void kernel_launch(void* const* d_in, const int* in_sizes, int n_in,
                              void* d_out, int out_size)
{
    const float* X   = (const float*)d_in[0];
    const float* W1  = (const float*)d_in[1];
    const float* b1  = (const float*)d_in[2];
    const float* g1  = (const float*)d_in[3];
    const float* be1 = (const float*)d_in[4];
    const float* W2  = (const float*)d_in[5];
    const float* b2  = (const float*)d_in[6];
    const float* CB  = (const float*)d_in[7];
    const float* W3  = (const float*)d_in[8];
    const float* b3  = (const float*)d_in[9];
    const float* g2  = (const float*)d_in[10];
    const float* be2 = (const float*)d_in[11];
    const float* W4  = (const float*)d_in[12];
    const float* b4  = (const float*)d_in[13];
    float* out = (float*)d_out;

    cudaFuncSetAttribute(encoder_kernel,     cudaFuncAttributeMaxDynamicSharedMemorySize, 98304);
    cudaFuncSetAttribute(dist_coarse_kernel, cudaFuncAttributeMaxDynamicSharedMemorySize, DSM2_TOT);
    cudaFuncSetAttribute(decoder_kernel,     cudaFuncAttributeMaxDynamicSharedMemorySize, DEC_SMEM);

    c0split_kernel<<<Kn / 8, 256>>>(CB);
    w4split_kernel<<<256, 256>>>(W4);
    encoder_kernel<<<Bn / 32, 256, 98304>>>(X, W1, b1, g1, be1, W2, b2);
    dist_coarse_kernel<<<Bn / 64, 256, DSM2_TOT>>>();
    rescore_kernel<<<Bn / 4, 128>>>(CB);
    decoder_kernel<<<Bn / 32, 256, DEC_SMEM>>>(CB, W3, b3, g2, be2, b4, X);
    reduce_kernel<<<1, 256>>>();
    final_kernel<<<Bn / 256, 256>>>(out);
}

// round 17
// speedup vs baseline: 1.0873x; 1.0048x over previous
#include <cuda_runtime.h>
#include <cuda_bf16.h>
#include <math.h>
#include <stdint.h>

#define Bn 16384
#define Dn 512
#define Kn 16384
#define Hn 256
#define Zn 128
#define LDK2 136                     // padded row stride in bf16 (272B); bytes 256..259 carry -0.5||c||^2

// ---------------- scratch ----------------
__device__ __align__(16) float g_enc[(size_t)Bn * Zn];
__device__ __align__(16) __nv_bfloat16 g_e0p[(size_t)Bn * LDK2];
__device__ __align__(16) __nv_bfloat16 g_c0p[(size_t)Kn * LDK2];
__device__ float g_negc2[Kn];
__device__ float g_en2[Bn];
__device__ float g_dn2[Bn];
__device__ float g_Rmax2;
__device__ float g_Nmax2;
__device__ float g_smax[Bn];
__device__ float g_cand_val[(size_t)Bn * 48];
__device__ int   g_cand_idx[(size_t)Bn * 48];
__device__ float g_fourth[(size_t)Bn * 16];
__device__ int   g_idx[Bn];
__device__ float g_err[Bn];
__device__ float g_sum;
// W4 pre-packed B-fragments: [s(16)][j(64)][p(2)][lane(32)] of uint2
__device__ __align__(16) uint2 g_W4f[16 * 64 * 2 * 32];

// ---------------- helpers ----------------
__device__ __forceinline__ uint32_t smem_u32(const void* p) {
    uint32_t a;
    asm("{ .reg .u64 t; cvta.to.shared.u64 t, %1; cvt.u32.u64 %0, t; }" : "=r"(a) : "l"(p));
    return a;
}
__device__ __forceinline__ void ldsm_x4(uint32_t r[4], uint32_t addr) {
    asm volatile("ldmatrix.sync.aligned.m8n8.x4.shared.b16 {%0,%1,%2,%3}, [%4];"
        : "=r"(r[0]), "=r"(r[1]), "=r"(r[2]), "=r"(r[3]) : "r"(addr));
}
__device__ __forceinline__ void mma_bf16(float d[4], const uint32_t a[4], const uint32_t b[2]) {
    asm volatile("mma.sync.aligned.m16n8k16.row.col.f32.bf16.bf16.f32 "
        "{%0,%1,%2,%3}, {%4,%5,%6,%7}, {%8,%9}, {%0,%1,%2,%3};"
        : "+f"(d[0]), "+f"(d[1]), "+f"(d[2]), "+f"(d[3])
        : "r"(a[0]), "r"(a[1]), "r"(a[2]), "r"(a[3]), "r"(b[0]), "r"(b[1]));
}
__device__ __forceinline__ uint32_t pack_bf16(float a, float b) {
    __nv_bfloat162 t = __floats2bfloat162_rn(a, b);
    return *(uint32_t*)&t;
}
// packed f32x2 helpers (PTX >= 8.6, sm_100+ base ISA)
__device__ __forceinline__ uint64_t packf2(float a, float b) {
    uint64_t r;
    asm("mov.b64 %0, {%1, %2};" : "=l"(r) : "f"(a), "f"(b));
    return r;
}
__device__ __forceinline__ void fma_f32x2(uint64_t& d, uint64_t a, uint64_t b) {
    asm("fma.rn.f32x2 %0, %1, %2, %0;" : "+l"(d) : "l"(a), "l"(b));
}
__device__ __forceinline__ void unpackf2(float& lo, float& hi, uint64_t v) {
    asm("mov.b64 {%0, %1}, %2;" : "=f"(lo), "=f"(hi) : "l"(v));
}
__device__ __forceinline__ void bulk_g2s(uint32_t dst, const void* src, uint32_t bytes, uint32_t mbar) {
    asm volatile("cp.async.bulk.shared::cluster.global.mbarrier::complete_tx::bytes [%0], [%1], %2, [%3];"
        :: "r"(dst), "l"(src), "r"(bytes), "r"(mbar) : "memory");
}
#define MBAR_INIT(mb, c) \
    asm volatile("mbarrier.init.shared.b64 [%0], %1;" :: "r"((uint32_t)(mb)), "r"((uint32_t)(c)) : "memory")
#define MBAR_EXPECT_TX(mb, n) \
    asm volatile("mbarrier.arrive.expect_tx.shared.b64 _, [%0], %1;" :: "r"((uint32_t)(mb)), "r"((uint32_t)(n)) : "memory")
#define MBAR_ARRIVE(mb) \
    asm volatile("mbarrier.arrive.shared.b64 _, [%0];" :: "r"((uint32_t)(mb)) : "memory")
#define MBAR_WAIT(mb, par) do { \
    uint32_t _m = (uint32_t)(mb); uint32_t _p = (uint32_t)(par); uint32_t _d; \
    asm volatile("{\n\t.reg .pred p;\n\t" \
        "mbarrier.try_wait.parity.acquire.cta.shared::cta.b64 p, [%1], %2;\n\t" \
        "selp.b32 %0, 1, 0, p;\n\t}" : "=r"(_d) : "r"(_m), "r"(_p) : "memory"); \
    if (!_d) { \
        asm volatile("{\n\t.reg .pred P1;\n\t" \
            "WL_%=:\n\t" \
            "mbarrier.try_wait.parity.acquire.cta.shared::cta.b64 P1, [%0], %1, 0x989680;\n\t" \
            "@P1 bra.uni WD_%=;\n\tbra.uni WL_%=;\n\tWD_%=:\n\t}" \
            :: "r"(_m), "r"(_p) : "memory"); \
    } } while (0)

// ---------------- encoder (R13 f32x2 GEMMs) + fused e0/norm epilogue ----------------
__global__ void encoder_kernel(const float* __restrict__ X,
                               const float* __restrict__ W1, const float* __restrict__ b1,
                               const float* __restrict__ g1, const float* __restrict__ be1,
                               const float* __restrict__ W2, const float* __restrict__ b2)
{
    extern __shared__ float sm[];
    float* Xs = sm;
    float* Hs = sm + 32 * Dn;
    const int tid = threadIdx.x;
    const int row0 = blockIdx.x * 32;

    {
        const float4* Xg = (const float4*)(X + (size_t)row0 * Dn);
        float4* Xs4 = (float4*)Xs;
        for (int i = tid; i < 32 * Dn / 4; i += 256) Xs4[i] = Xg[i];
    }
    __syncthreads();

    // GEMM1: thread -> cols (c, c+128), rows rbase..rbase+15, packed f32x2
    {
        const float4* Xs4 = (const float4*)Xs;
        const int c = tid & 127;
        const int rbase = (tid >> 7) * 16;
        uint64_t acc2[16];
#pragma unroll
        for (int r = 0; r < 16; ++r) acc2[r] = 0ull;
        for (int d = 0; d < Dn; d += 4) {
            uint64_t wp[4];
#pragma unroll
            for (int j = 0; j < 4; ++j)
                wp[j] = packf2(W1[(d + j) * Hn + c], W1[(d + j) * Hn + c + 128]);
#pragma unroll
            for (int r = 0; r < 16; ++r) {
                float4 x = Xs4[((rbase + r) * Dn + d) >> 2];
                fma_f32x2(acc2[r], packf2(x.x, x.x), wp[0]);
                fma_f32x2(acc2[r], packf2(x.y, x.y), wp[1]);
                fma_f32x2(acc2[r], packf2(x.z, x.z), wp[2]);
                fma_f32x2(acc2[r], packf2(x.w, x.w), wp[3]);
            }
        }
        float bba = b1[c], bbb = b1[c + 128];
#pragma unroll
        for (int r = 0; r < 16; ++r) {
            float lo, hi;
            unpackf2(lo, hi, acc2[r]);
            Hs[(rbase + r) * Hn + c]       = lo + bba;
            Hs[(rbase + r) * Hn + c + 128] = hi + bbb;
        }
    }
    __syncthreads();

    // LN + GELU
    {
        const int warp = tid >> 5, lane = tid & 31;
        for (int rr = 0; rr < 4; ++rr) {
            int r = warp + rr * 8;
            float s = 0.f, s2 = 0.f;
#pragma unroll
            for (int j = 0; j < 8; ++j) {
                float v = Hs[r * Hn + lane + j * 32];
                s += v; s2 += v * v;
            }
#pragma unroll
            for (int o = 16; o > 0; o >>= 1) {
                s  += __shfl_xor_sync(0xffffffff, s,  o);
                s2 += __shfl_xor_sync(0xffffffff, s2, o);
            }
            float mu  = s * (1.f / Hn);
            float var = s2 * (1.f / Hn) - mu * mu;
            float inv = rsqrtf(var + 1e-5f);
#pragma unroll
            for (int j = 0; j < 8; ++j) {
                int c = lane + j * 32;
                float v = (Hs[r * Hn + c] - mu) * inv * g1[c] + be1[c];
                Hs[r * Hn + c] = 0.5f * v * (1.f + erff(v * 0.70710678118654752f));
            }
        }
    }
    __syncthreads();

    // GEMM2 + fused e0/norm epilogue
    {
        const float4* Hs4 = (const float4*)Hs;
        const int c2 = tid & 63;
        const int rbase = (tid >> 6) * 8;
        uint64_t acc2[8];
#pragma unroll
        for (int r = 0; r < 8; ++r) acc2[r] = 0ull;
        for (int d = 0; d < Hn; d += 4) {
            uint64_t wp[4];
#pragma unroll
            for (int j = 0; j < 4; ++j)
                wp[j] = packf2(W2[(d + j) * Zn + c2], W2[(d + j) * Zn + c2 + 64]);
#pragma unroll
            for (int r = 0; r < 8; ++r) {
                float4 h = Hs4[((rbase + r) * Hn + d) >> 2];
                fma_f32x2(acc2[r], packf2(h.x, h.x), wp[0]);
                fma_f32x2(acc2[r], packf2(h.y, h.y), wp[1]);
                fma_f32x2(acc2[r], packf2(h.z, h.z), wp[2]);
                fma_f32x2(acc2[r], packf2(h.w, h.w), wp[3]);
            }
        }
        float bba = b2[c2], bbb = b2[c2 + 64];
        float pen[8], pdn[8];
#pragma unroll
        for (int r = 0; r < 8; ++r) {
            float lo, hi;
            unpackf2(lo, hi, acc2[r]);
            float va = lo + bba;
            float vb = hi + bbb;
            size_t grow = (size_t)(row0 + rbase + r);
            g_enc[grow * Zn + c2]      = va;
            g_enc[grow * Zn + c2 + 64] = vb;
            __nv_bfloat16 ba = __float2bfloat16(va);
            __nv_bfloat16 bb16 = __float2bfloat16(vb);
            g_e0p[grow * LDK2 + c2]      = ba;
            g_e0p[grow * LDK2 + c2 + 64] = bb16;
            float fa = __bfloat162float(ba), fb = __bfloat162float(bb16);
            float da = va - fa, db = vb - fb;
            pen[r] = va * va + vb * vb;
            pdn[r] = da * da + db * db;
        }
        const int warp = tid >> 5, lane = tid & 31;
        float* epn = Xs;
        float* edn = Xs + 64;
#pragma unroll
        for (int r = 0; r < 8; ++r) {
            float a = pen[r], bsum = pdn[r];
#pragma unroll
            for (int o = 16; o > 0; o >>= 1) {
                a    += __shfl_xor_sync(0xffffffff, a,    o);
                bsum += __shfl_xor_sync(0xffffffff, bsum, o);
            }
            if (lane == 0) {
                epn[(rbase + r) * 2 + (warp & 1)] = a;
                edn[(rbase + r) * 2 + (warp & 1)] = bsum;
            }
        }
        __syncthreads();
        if (tid < 32) {
            g_en2[row0 + tid] = epn[tid * 2] + epn[tid * 2 + 1];
            g_dn2[row0 + tid] = edn[tid * 2] + edn[tid * 2 + 1];
        }
    }
}

// ---------------- fused prep: codebook bf16+nc (blocks < 2048) | W4 fragments ----------------
__global__ void prep_kernel(const float* __restrict__ C, const float* __restrict__ W4)
{
    if (blockIdx.x < 2048) {
        int code = (blockIdx.x * 256 + threadIdx.x) >> 5;
        int lane = threadIdx.x & 31;
        const float4 c4 = ((const float4*)(C + (size_t)code * 128))[lane];
        float c0x = __bfloat162float(__float2bfloat16(c4.x));
        float c0y = __bfloat162float(__float2bfloat16(c4.y));
        float c0z = __bfloat162float(__float2bfloat16(c4.z));
        float c0w = __bfloat162float(__float2bfloat16(c4.w));
        *(uint2*)(g_c0p + (size_t)code * LDK2 + lane * 4) =
            make_uint2(pack_bf16(c4.x, c4.y), pack_bf16(c4.z, c4.w));
        float c2 = c4.x*c4.x + c4.y*c4.y + c4.z*c4.z + c4.w*c4.w;
        float n2 = c0x*c0x + c0y*c0y + c0z*c0z + c0w*c0w;
        float dx = c4.x - c0x, dy = c4.y - c0y, dz = c4.z - c0z, dw = c4.w - c0w;
        float r2 = dx*dx + dy*dy + dz*dz + dw*dw;
#pragma unroll
        for (int o = 16; o > 0; o >>= 1) {
            c2 += __shfl_xor_sync(0xffffffff, c2, o);
            n2 += __shfl_xor_sync(0xffffffff, n2, o);
            r2 += __shfl_xor_sync(0xffffffff, r2, o);
        }
        if (lane == 0) {
            float nc = -0.5f * c2;
            g_negc2[code] = nc;
            *(float*)((char*)g_c0p + (size_t)code * (LDK2 * 2) + 256) = nc;
            atomicMax((int*)&g_Rmax2, __float_as_int(r2));
            atomicMax((int*)&g_Nmax2, __float_as_int(n2));
        }
    } else {
        int i = (blockIdx.x - 2048) * 256 + threadIdx.x;
        int lane = i & 31;
        int p = (i >> 5) & 1;
        int j = (i >> 6) & 63;
        int s = i >> 12;
        int n = j * 8 + (lane >> 2);
        uint32_t regs[2];
#pragma unroll
        for (int r = 0; r < 2; ++r) {
            int k = s * 16 + (lane & 3) * 2 + r * 8;
            float wa = W4[(size_t)k * Dn + n];
            float wb = W4[(size_t)(k + 1) * Dn + n];
            float va, vb;
            if (p == 0) {
                va = __bfloat162float(__float2bfloat16(wa));
                vb = __bfloat162float(__float2bfloat16(wb));
            } else {
                va = wa - __bfloat162float(__float2bfloat16(wa));
                vb = wb - __bfloat162float(__float2bfloat16(wb));
            }
            regs[r] = pack_bf16(va, vb);
        }
        g_W4f[i] = make_uint2(regs[0], regs[1]);
    }
}

// ---------------- coarse distance: mbarrier ring; nc folded into acc init ----------------
#define A_BYTES (64 * LDK2 * 2)
#define TILE_BYTES (128 * LDK2 * 2)
#define SB_A 0
#define SB_B0 A_BYTES
#define SB_MBAR (A_BYTES + 2 * TILE_BYTES)
#define SB_RED (SB_MBAR + 64)
#define DSM2_TOT (SB_RED + 64 * 16 * 4)

__global__ __launch_bounds__(256, 2) void dist_coarse_kernel()
{
    extern __shared__ char smem[];
    float* redsm = (float*)(smem + SB_RED);

    const int tid  = threadIdx.x;
    const int lane = tid & 31;
    const int wid  = tid >> 5;
    const int warp_m = wid >> 2;
    const int warp_n = wid & 3;
    const int row0 = blockIdx.x * 64;

    const uint32_t sbA    = smem_u32(smem) + SB_A;
    const uint32_t sbB0   = smem_u32(smem) + SB_B0;
    const uint32_t mbA    = smem_u32(smem) + SB_MBAR;
    const uint32_t mbF0   = mbA + 8;
    const uint32_t mbF1   = mbA + 16;
    const uint32_t mbE0   = mbA + 24;
    const uint32_t mbE1   = mbA + 32;

    if (tid == 0) {
        MBAR_INIT(mbA, 1);
        MBAR_INIT(mbF0, 1);
        MBAR_INIT(mbF1, 1);
        MBAR_INIT(mbE0, 8);
        MBAR_INIT(mbE1, 8);
    }
    __syncthreads();

    if (tid == 0) {
        MBAR_EXPECT_TX(mbA, A_BYTES);
        bulk_g2s(sbA, g_e0p + (size_t)row0 * LDK2, A_BYTES, mbA);
        MBAR_EXPECT_TX(mbF0, TILE_BYTES);
        bulk_g2s(sbB0, g_c0p, TILE_BYTES, mbF0);
    }

    uint32_t a_addr[2];
#pragma unroll
    for (int mi = 0; mi < 2; ++mi)
        a_addr[mi] = sbA + ((warp_m * 32 + mi * 16 + (lane & 15)) * LDK2 + (lane >> 4) * 8) * 2;
    uint32_t b_addr[2];
#pragma unroll
    for (int njp = 0; njp < 2; ++njp)
        b_addr[njp] = sbB0 + ((warp_n * 32 + njp * 16 + (lane & 7) + ((lane >> 4) << 3)) * LDK2
                              + ((lane >> 3) & 1) * 8) * 2;

    float v1[4], v2[4], v3[4], v4[4];
    int   i1[4], i2[4], i3[4];
#pragma unroll
    for (int r = 0; r < 4; ++r) {
        v1[r] = v2[r] = v3[r] = v4[r] = -INFINITY;
        i1[r] = i2[r] = i3[r] = 0;
    }

    const int cq = (lane & 3) * 2;

    MBAR_WAIT(mbA, 0);

    for (int t = 0, kt = 0; t < 128; ++t, kt += 128) {
        const uint32_t bufo = (uint32_t)(t & 1) * TILE_BYTES;

        if (tid == 0 && t < 127) {
            const int tn = t + 1;
            const int bn = tn & 1;
            const int f  = tn >> 1;
            uint32_t mbE = bn ? mbE1 : mbE0;
            uint32_t mbF = bn ? mbF1 : mbF0;
            if (f > 0) MBAR_WAIT(mbE, (f & 1) ^ 1);
            MBAR_EXPECT_TX(mbF, TILE_BYTES);
            bulk_g2s(sbB0 + (uint32_t)bn * TILE_BYTES,
                     g_c0p + (size_t)(kt + 128) * LDK2, TILE_BYTES, mbF);
        }

        MBAR_WAIT((t & 1) ? mbF1 : mbF0, (t >> 1) & 1);

        float nc[8];
#pragma unroll
        for (int nj = 0; nj < 4; ++nj) {
#pragma unroll
            for (int q = 0; q < 2; ++q) {
                asm volatile("ld.shared.f32 %0, [%1];"
                    : "=f"(nc[nj * 2 + q])
                    : "r"(sbB0 + bufo + (uint32_t)(warp_n * 32 + nj * 8 + cq + q) * (LDK2 * 2) + 256));
            }
        }

        float acc[2][4][4];
#pragma unroll
        for (int mi = 0; mi < 2; ++mi)
#pragma unroll
            for (int nj = 0; nj < 4; ++nj)
#pragma unroll
                for (int k = 0; k < 4; ++k) acc[mi][nj][k] = nc[nj * 2 + (k & 1)];

        // hoisted per-tile B bases
        const uint32_t b0a = b_addr[0] + bufo;
        const uint32_t b1a = b_addr[1] + bufo;

#pragma unroll
        for (int s = 0; s < 8; ++s) {
            uint32_t af[2][4], bf[2][4];
#pragma unroll
            for (int mi = 0; mi < 2; ++mi) ldsm_x4(af[mi], a_addr[mi] + s * 32);
            ldsm_x4(bf[0], b0a + s * 32);
            ldsm_x4(bf[1], b1a + s * 32);
#pragma unroll
            for (int mi = 0; mi < 2; ++mi)
#pragma unroll
                for (int nj = 0; nj < 4; ++nj)
                    mma_bf16(acc[mi][nj], af[mi], bf[nj >> 1] + (nj & 1) * 2);
        }

        if (lane == 0) MBAR_ARRIVE((t & 1) ? mbE1 : mbE0);

#pragma unroll
        for (int mi = 0; mi < 2; ++mi) {
#pragma unroll
            for (int h = 0; h < 2; ++h) {
                const int ri = mi * 2 + h;
                float s0 = acc[mi][0][h * 2];
                float s1 = acc[mi][0][h * 2 + 1];
                float s2 = acc[mi][1][h * 2];
                float s3 = acc[mi][1][h * 2 + 1];
                float s4 = acc[mi][2][h * 2];
                float s5 = acc[mi][2][h * 2 + 1];
                float s6 = acc[mi][3][h * 2];
                float s7 = acc[mi][3][h * 2 + 1];
                float m8 = fmaxf(fmaxf(fmaxf(s0, s1), fmaxf(s2, s3)),
                                 fmaxf(fmaxf(s4, s5), fmaxf(s6, s7)));
                if (m8 > v4[ri]) {
                    float sv[8] = {s0, s1, s2, s3, s4, s5, s6, s7};
#pragma unroll
                    for (int j = 0; j < 8; ++j) {
                        float v = sv[j];
                        if (v > v4[ri]) {
                            int idx = kt + warp_n * 32 + (j >> 1) * 8 + cq + (j & 1);
                            if (v > v1[ri]) {
                                v4[ri] = v3[ri]; v3[ri] = v2[ri]; i3[ri] = i2[ri];
                                v2[ri] = v1[ri]; i2[ri] = i1[ri];
                                v1[ri] = v; i1[ri] = idx;
                            } else if (v > v2[ri]) {
                                v4[ri] = v3[ri]; v3[ri] = v2[ri]; i3[ri] = i2[ri];
                                v2[ri] = v; i2[ri] = idx;
                            } else if (v > v3[ri]) {
                                v4[ri] = v3[ri]; v3[ri] = v; i3[ri] = idx;
                            } else {
                                v4[ri] = v;
                            }
                        }
                    }
                }
            }
        }
    }

    const int slot = warp_n * 4 + (lane & 3);
#pragma unroll
    for (int ri = 0; ri < 4; ++ri) {
        int mi = ri >> 1, h = ri & 1;
        int lrow = warp_m * 32 + mi * 16 + (lane >> 2) + h * 8;
        size_t row = (size_t)(row0 + lrow);
        g_cand_val[row * 48 + slot * 3]     = v1[ri];
        g_cand_idx[row * 48 + slot * 3]     = i1[ri];
        g_cand_val[row * 48 + slot * 3 + 1] = v2[ri];
        g_cand_idx[row * 48 + slot * 3 + 1] = i2[ri];
        g_cand_val[row * 48 + slot * 3 + 2] = v3[ri];
        g_cand_idx[row * 48 + slot * 3 + 2] = i3[ri];
        g_fourth[row * 16 + slot] = v4[ri];
        redsm[lrow * 16 + slot] = v1[ri];
    }
    __syncthreads();
    if (tid < 64) {
        float m = redsm[tid * 16];
#pragma unroll
        for (int w = 1; w < 16; ++w) m = fmaxf(m, redsm[tid * 16 + w]);
        g_smax[row0 + tid] = m;
    }
}

// ---------------- exact rescore (warp per row), slot-sorted early skip ----------------
__global__ void rescore_kernel(const float* __restrict__ CB)
{
    const int r = blockIdx.x * 4 + (threadIdx.x >> 5);
    const int lane = threadIdx.x & 31;

    float delta = sqrtf(g_en2[r]) * sqrtf(g_Rmax2) + sqrtf(g_dn2[r]) * sqrtf(g_Nmax2);
    float thresh = g_smax[r] - 1.05f * delta - 1e-4f;

    float th = (lane < 16) ? g_fourth[(size_t)r * 16 + lane] : -INFINITY;
    bool flag = __ballot_sync(0xffffffff, th >= thresh) != 0;

    const float4 e4 = ((const float4*)(g_enc + (size_t)r * 128))[lane];

    float bs = -INFINITY;
    int bi = 0x7fffffff;

    if (!flag) {
        // each 3-slot triple is sorted descending: gate on its top value
        for (int s16 = 0; s16 < 16; ++s16) {
            size_t base = (size_t)r * 48 + s16 * 3;
            if (g_cand_val[base] < thresh) continue;
#pragma unroll
            for (int q = 0; q < 3; ++q) {
                float v = g_cand_val[base + q];
                if (v < thresh) break;
                int idx = g_cand_idx[base + q];
                float4 c4 = ((const float4*)(CB + (size_t)idx * 128))[lane];
                float d = e4.x*c4.x + e4.y*c4.y + e4.z*c4.z + e4.w*c4.w;
#pragma unroll
                for (int o = 16; o > 0; o >>= 1) d += __shfl_xor_sync(0xffffffff, d, o);
                float sx = d + g_negc2[idx];
                if (sx > bs || (sx == bs && idx < bi)) { bs = sx; bi = idx; }
            }
        }
    } else {
        for (int k = 0; k < Kn; ++k) {
            float4 c4 = ((const float4*)(CB + (size_t)k * 128))[lane];
            float d = e4.x*c4.x + e4.y*c4.y + e4.z*c4.z + e4.w*c4.w;
#pragma unroll
            for (int o = 16; o > 0; o >>= 1) d += __shfl_xor_sync(0xffffffff, d, o);
            float sx = d + g_negc2[k];
            if (sx > bs) { bs = sx; bi = k; }
        }
    }
    if (lane == 0) g_idx[r] = bi;
}

// ---------------- decoder: f32x2 GEMM1 (inline W3 pack), mma GEMM2 ----------------
#define DEC_HS0_OFF (32 * Zn + 32 * Hn)
#define DEC_LDH 264
#define DEC_SMEM (12288 * 4 + 2 * 32 * DEC_LDH * 2 + 32 * 8 * 4)

__global__ void decoder_kernel(const float* __restrict__ C,
                               const float* __restrict__ W3, const float* __restrict__ b3,
                               const float* __restrict__ g2, const float* __restrict__ be2,
                               const float* __restrict__ b4,
                               const float* __restrict__ X)
{
    extern __shared__ float sm[];
    float* Qs = sm;
    float* Hs = sm + 32 * Zn;
    __nv_bfloat16* Hs0 = (__nv_bfloat16*)(sm + DEC_HS0_OFF);
    __nv_bfloat16* Hs1 = Hs0 + 32 * DEC_LDH;
    float* ep = (float*)(Hs1 + 32 * DEC_LDH);
    const int tid = threadIdx.x;
    const int lane = tid & 31;
    const int wid = tid >> 5;
    const int row0 = blockIdx.x * 32;

    for (int i = tid; i < 32 * 32; i += 256) {
        int r = i >> 5, d4 = i & 31;
        int code = g_idx[row0 + r];
        ((float4*)Qs)[r * 32 + d4] = ((const float4*)C)[(size_t)code * 32 + d4];
    }
    __syncthreads();

    // f32x2 GEMM1
    {
        const float4* Qs4 = (const float4*)Qs;
        const int c = tid & 127;
        const int rbase = (tid >> 7) * 16;
        uint64_t acc2[16];
#pragma unroll
        for (int r = 0; r < 16; ++r) acc2[r] = 0ull;
        for (int d = 0; d < Zn; d += 4) {
            uint64_t wp[4];
#pragma unroll
            for (int j = 0; j < 4; ++j)
                wp[j] = packf2(W3[(d + j) * Hn + c], W3[(d + j) * Hn + c + 128]);
#pragma unroll
            for (int r = 0; r < 16; ++r) {
                float4 q = Qs4[((rbase + r) * Zn + d) >> 2];
                fma_f32x2(acc2[r], packf2(q.x, q.x), wp[0]);
                fma_f32x2(acc2[r], packf2(q.y, q.y), wp[1]);
                fma_f32x2(acc2[r], packf2(q.z, q.z), wp[2]);
                fma_f32x2(acc2[r], packf2(q.w, q.w), wp[3]);
            }
        }
        float bba = b3[c], bbb = b3[c + 128];
#pragma unroll
        for (int r = 0; r < 16; ++r) {
            float lo, hi;
            unpackf2(lo, hi, acc2[r]);
            Hs[(rbase + r) * Hn + c]       = lo + bba;
            Hs[(rbase + r) * Hn + c + 128] = hi + bbb;
        }
    }
    __syncthreads();

    {
        for (int rr = 0; rr < 4; ++rr) {
            int r = wid + rr * 8;
            float s = 0.f, s2 = 0.f;
#pragma unroll
            for (int j = 0; j < 8; ++j) {
                float v = Hs[r * Hn + lane + j * 32];
                s += v; s2 += v * v;
            }
#pragma unroll
            for (int o = 16; o > 0; o >>= 1) {
                s  += __shfl_xor_sync(0xffffffff, s,  o);
                s2 += __shfl_xor_sync(0xffffffff, s2, o);
            }
            float mu  = s * (1.f / Hn);
            float var = s2 * (1.f / Hn) - mu * mu;
            float inv = rsqrtf(var + 1e-5f);
#pragma unroll
            for (int j = 0; j < 8; ++j) {
                int c = lane + j * 32;
                float v = (Hs[r * Hn + c] - mu) * inv * g2[c] + be2[c];
                Hs[r * Hn + c] = 0.5f * v * (1.f + erff(v * 0.70710678118654752f));
            }
        }
    }
    __syncthreads();

    for (int i = tid; i < 32 * 256; i += 256) {
        int r = i >> 8, c = i & 255;
        float f = Hs[r * Hn + c];
        __nv_bfloat16 h0 = __float2bfloat16(f);
        Hs0[r * DEC_LDH + c] = h0;
        Hs1[r * DEC_LDH + c] = __float2bfloat16(f - __bfloat162float(h0));
    }
    __syncthreads();

    {
        const uint32_t h0b = smem_u32(Hs0);
        const uint32_t h1b = smem_u32(Hs1);
        uint32_t a0_addr[2], a1_addr[2];
#pragma unroll
        for (int mi = 0; mi < 2; ++mi) {
            uint32_t off = (uint32_t)((mi * 16 + (lane & 15)) * DEC_LDH * 2 + (lane >> 4) * 16);
            a0_addr[mi] = h0b + off;
            a1_addr[mi] = h1b + off;
        }

        float e_part[2][2] = {{0.f, 0.f}, {0.f, 0.f}};

#pragma unroll
        for (int h2 = 0; h2 < 2; ++h2) {
            float acc[2][4][4];
#pragma unroll
            for (int mi = 0; mi < 2; ++mi)
#pragma unroll
                for (int nj = 0; nj < 4; ++nj)
#pragma unroll
                    for (int k = 0; k < 4; ++k) acc[mi][nj][k] = 0.f;

            const int j0 = wid * 8 + h2 * 4;
            for (int s = 0; s < 16; ++s) {
                uint32_t a0[2][4], a1[2][4];
#pragma unroll
                for (int mi = 0; mi < 2; ++mi) {
                    ldsm_x4(a0[mi], a0_addr[mi] + s * 32);
                    ldsm_x4(a1[mi], a1_addr[mi] + s * 32);
                }
                uint32_t b0[4][2], b1[4][2];
#pragma unroll
                for (int nj = 0; nj < 4; ++nj) {
                    uint2 v = g_W4f[(size_t)(((s * 64 + j0 + nj) * 2 + 0) * 32 + lane)];
                    b0[nj][0] = v.x; b0[nj][1] = v.y;
                    uint2 w = g_W4f[(size_t)(((s * 64 + j0 + nj) * 2 + 1) * 32 + lane)];
                    b1[nj][0] = w.x; b1[nj][1] = w.y;
                }
#pragma unroll
                for (int mi = 0; mi < 2; ++mi)
#pragma unroll
                    for (int nj = 0; nj < 4; ++nj) {
                        mma_bf16(acc[mi][nj], a0[mi], b0[nj]);
                        mma_bf16(acc[mi][nj], a1[mi], b0[nj]);
                        mma_bf16(acc[mi][nj], a0[mi], b1[nj]);
                    }
            }

#pragma unroll
            for (int nj = 0; nj < 4; ++nj) {
                int col = wid * 64 + h2 * 32 + nj * 8 + (lane & 3) * 2;
                float2 bb = *(const float2*)(b4 + col);
#pragma unroll
                for (int mi = 0; mi < 2; ++mi) {
#pragma unroll
                    for (int hr = 0; hr < 2; ++hr) {
                        int rowg = row0 + mi * 16 + (lane >> 2) + hr * 8;
                        float2 xx = *(const float2*)(X + (size_t)rowg * Dn + col);
                        float d0 = acc[mi][nj][hr * 2]     + bb.x - xx.x;
                        float d1 = acc[mi][nj][hr * 2 + 1] + bb.y - xx.y;
                        e_part[mi][hr] += d0 * d0 + d1 * d1;
                    }
                }
            }
        }

#pragma unroll
        for (int mi = 0; mi < 2; ++mi)
#pragma unroll
            for (int hr = 0; hr < 2; ++hr) {
                float v = e_part[mi][hr];
                v += __shfl_xor_sync(0xffffffff, v, 1);
                v += __shfl_xor_sync(0xffffffff, v, 2);
                if ((lane & 3) == 0)
                    ep[(mi * 16 + (lane >> 2) + hr * 8) * 8 + wid] = v;
            }
    }
    __syncthreads();
    if (tid < 32) {
        float s = 0.f;
#pragma unroll
        for (int w = 0; w < 8; ++w) s += ep[tid * 8 + w];
        g_err[row0 + tid] = s * (1.f / Dn);
    }
}

// ---------------- global mean ----------------
__global__ void reduce_kernel()
{
    __shared__ float s[256];
    int tid = threadIdx.x;
    float a = 0.f;
    for (int i = tid; i < Bn; i += 256) a += g_err[i];
    s[tid] = a;
    __syncthreads();
    for (int o = 128; o > 0; o >>= 1) {
        if (tid < o) s[tid] += s[tid + o];
        __syncthreads();
    }
    if (tid == 0) g_sum = s[0];
}

// ---------------- MDL + output ----------------
__global__ void final_kernel(float* __restrict__ out)
{
    int i = blockIdx.x * 256 + threadIdx.x;
    float scale = g_sum * (1.f / Bn) + 1e-8f;
    float err = g_err[i];
    float eb = (fabsf(err) / scale + logf(2.f * scale)) * 1.4426950408889634f;
    float tb = 14.f + eb;
    out[i]          = err;
    out[Bn + i]     = (Dn * 32.f) / tb;
    out[2 * Bn + i] = tb;
    out[3 * Bn + i] = (float)g_idx[i];
}

// ---------------- launch ----------------
extern "C" void kernel_launch(void* const* d_in, const int* in_sizes, int n_in,
                              void* d_out, int out_size)
{
    const float* X   = (const float*)d_in[0];
    const float* W1  = (const float*)d_in[1];
    const float* b1  = (const float*)d_in[2];
    const float* g1  = (const float*)d_in[3];
    const float* be1 = (const float*)d_in[4];
    const float* W2  = (const float*)d_in[5];
    const float* b2  = (const float*)d_in[6];
    const float* CB  = (const float*)d_in[7];
    const float* W3  = (const float*)d_in[8];
    const float* b3  = (const float*)d_in[9];
    const float* g2  = (const float*)d_in[10];
    const float* be2 = (const float*)d_in[11];
    const float* W4  = (const float*)d_in[12];
    const float* b4  = (const float*)d_in[13];
    float* out = (float*)d_out;

    cudaFuncSetAttribute(encoder_kernel,     cudaFuncAttributeMaxDynamicSharedMemorySize, 98304);
    cudaFuncSetAttribute(dist_coarse_kernel, cudaFuncAttributeMaxDynamicSharedMemorySize, DSM2_TOT);
    cudaFuncSetAttribute(decoder_kernel,     cudaFuncAttributeMaxDynamicSharedMemorySize, DEC_SMEM);

    prep_kernel<<<2304, 256>>>(CB, W4);
    encoder_kernel<<<Bn / 32, 256, 98304>>>(X, W1, b1, g1, be1, W2, b2);
    dist_coarse_kernel<<<Bn / 64, 256, DSM2_TOT>>>();
    rescore_kernel<<<Bn / 4, 128>>>(CB);
    decoder_kernel<<<Bn / 32, 256, DEC_SMEM>>>(CB, W3, b3, g2, be2, b4, X);
    reduce_kernel<<<1, 256>>>();
    final_kernel<<<Bn / 256, 256>>>(out);
}